// round 2
// baseline (speedup 1.0000x reference)
#include <cuda_runtime.h>
#include <math.h>

#define NU 60000
#define NI 120000
#define NT 180000   // NU + NI

// ---------------- device scratch (static allocation is the sanctioned path) ----
__device__ float g_spmm[(size_t)NT * 64];   // spmm output scratch
__device__ float g_hid [(size_t)NI * 64];   // MLP hidden (max of NU/NI rows)
__device__ float g_uh  [(size_t)NU * 64];   // final user MLP output (pre-relu)
__device__ float g_ih  [(size_t)NI * 64];   // final item MLP output (pre-relu)
__device__ float g_ego [(size_t)NT * 64];   // current layer embeddings
__device__ float g_all [(size_t)NT * 256];  // concatenated [ego0 | n1 | n2 | n3]

// ---------------- zero ---------------------------------------------------------
__global__ void zero4_kernel(float4* __restrict__ p, int n4) {
    int i = blockIdx.x * blockDim.x + threadIdx.x;
    int s = gridDim.x * blockDim.x;
    float4 z = make_float4(0.f, 0.f, 0.f, 0.f);
    for (; i < n4; i += s) p[i] = z;
}

// ---------------- COO SpMM: out[row] += val * x[col], 16 threads / nnz ---------
__global__ void spmm_kernel(const int* __restrict__ rows, const int* __restrict__ cols,
                            const float* __restrict__ vals, const float* __restrict__ x,
                            float* __restrict__ out, int nnz) {
    int tid = blockIdx.x * blockDim.x + threadIdx.x;
    int e = tid >> 4;
    if (e >= nnz) return;
    int f = (tid & 15) << 2;               // float offset 0..60, 16B aligned
    int r = __ldg(rows + e);
    int c = __ldg(cols + e);
    float v = __ldg(vals + e);
    float4 xv = *reinterpret_cast<const float4*>(x + (size_t)c * 64 + f);
    float* dst = out + (size_t)r * 64 + f;
    asm volatile("red.global.add.v4.f32 [%0], {%1,%2,%3,%4};"
                 :: "l"(dst), "f"(v * xv.x), "f"(v * xv.y), "f"(v * xv.z), "f"(v * xv.w)
                 : "memory");
}

// ---------------- GEMM: Y = act(X[R,64] @ W[64,64] + b), row-per-thread --------
// ACT: 0 = identity, 1 = elu
template <int ACT>
__global__ void __launch_bounds__(64) gemm64_kernel(
    const float* __restrict__ X, const float* __restrict__ W,
    const float* __restrict__ b, float* __restrict__ Y, int R) {
    __shared__ float Ws[4096];
    __shared__ float xs[4096];   // transposed: xs[k*64 + lane] = X[row_lane][k]
    int tid = threadIdx.x;
    for (int i = tid; i < 4096; i += 64) Ws[i] = W[i];
    int row = blockIdx.x * 64 + tid;
    bool valid = row < R;
    if (valid) {
        const float4* xp = reinterpret_cast<const float4*>(X + (size_t)row * 64);
#pragma unroll
        for (int i = 0; i < 16; i++) {
            float4 t = xp[i];
            xs[(4 * i + 0) * 64 + tid] = t.x;
            xs[(4 * i + 1) * 64 + tid] = t.y;
            xs[(4 * i + 2) * 64 + tid] = t.z;
            xs[(4 * i + 3) * 64 + tid] = t.w;
        }
    }
    __syncthreads();
    if (!valid) return;

    float acc[64];
#pragma unroll
    for (int j = 0; j < 64; j++) acc[j] = __ldg(b + j);

    for (int k = 0; k < 64; k++) {
        float xv = xs[k * 64 + tid];
        const float4* wr = reinterpret_cast<const float4*>(Ws + k * 64);
#pragma unroll
        for (int j = 0; j < 16; j++) {
            float4 w = wr[j];
            acc[4 * j + 0] += xv * w.x;
            acc[4 * j + 1] += xv * w.y;
            acc[4 * j + 2] += xv * w.z;
            acc[4 * j + 3] += xv * w.w;
        }
    }

    float4* yp = reinterpret_cast<float4*>(Y + (size_t)row * 64);
#pragma unroll
    for (int i = 0; i < 16; i++) {
        float a0 = acc[4 * i + 0], a1 = acc[4 * i + 1];
        float a2 = acc[4 * i + 2], a3 = acc[4 * i + 3];
        if (ACT == 1) {
            a0 = a0 > 0.f ? a0 : expm1f(a0);
            a1 = a1 > 0.f ? a1 : expm1f(a1);
            a2 = a2 > 0.f ? a2 : expm1f(a2);
            a3 = a3 > 0.f ? a3 : expm1f(a3);
        }
        yp[i] = make_float4(a0, a1, a2, a3);
    }
}

// ---------------- Fused NGCF layer ---------------------------------------------
// ego_new = leaky_relu(side@Wg + bg + (ego*side)@Wb + bb, 0.2)
// g_ego <- ego_new ; g_all[:, kout*64 : +64] <- l2norm(ego_new)
__global__ void __launch_bounds__(64) layer_kernel(
    const float* __restrict__ Wg, const float* __restrict__ bg,
    const float* __restrict__ Wb, const float* __restrict__ bb, int kout) {
    __shared__ float Wgs[4096];
    __shared__ float Wbs[4096];
    __shared__ float ss[4096];   // transposed side tile [k][lane]
    int tid = threadIdx.x;
    for (int i = tid; i < 4096; i += 64) { Wgs[i] = Wg[i]; Wbs[i] = Wb[i]; }
    int row = blockIdx.x * 64 + tid;
    bool valid = row < NT;
    if (valid) {
        const float4* sp = reinterpret_cast<const float4*>(g_spmm + (size_t)row * 64);
#pragma unroll
        for (int i = 0; i < 16; i++) {
            float4 t = sp[i];
            ss[(4 * i + 0) * 64 + tid] = t.x;
            ss[(4 * i + 1) * 64 + tid] = t.y;
            ss[(4 * i + 2) * 64 + tid] = t.z;
            ss[(4 * i + 3) * 64 + tid] = t.w;
        }
    }
    __syncthreads();
    if (!valid) return;

    float acc[64];
#pragma unroll
    for (int j = 0; j < 64; j++) acc[j] = __ldg(bg + j) + __ldg(bb + j);

    const float* erow = g_ego + (size_t)row * 64;
    for (int k = 0; k < 64; k++) {
        float s = ss[k * 64 + tid];
        float p = s * __ldg(erow + k);
        const float4* wg = reinterpret_cast<const float4*>(Wgs + k * 64);
        const float4* wb = reinterpret_cast<const float4*>(Wbs + k * 64);
#pragma unroll
        for (int j = 0; j < 16; j++) {
            float4 a = wg[j];
            float4 c = wb[j];
            acc[4 * j + 0] += s * a.x + p * c.x;
            acc[4 * j + 1] += s * a.y + p * c.y;
            acc[4 * j + 2] += s * a.z + p * c.z;
            acc[4 * j + 3] += s * a.w + p * c.w;
        }
    }

    float ssum = 0.f;
#pragma unroll
    for (int j = 0; j < 64; j++) {
        float v = acc[j];
        v = v >= 0.f ? v : 0.2f * v;   // leaky_relu slope 0.2
        acc[j] = v;
        ssum += v * v;
    }
    float inv = 1.f / fmaxf(sqrtf(ssum), 1e-12f);

    float4* ep = reinterpret_cast<float4*>(g_ego + (size_t)row * 64);
    float4* ap = reinterpret_cast<float4*>(g_all + (size_t)row * 256 + (size_t)kout * 64);
#pragma unroll
    for (int i = 0; i < 16; i++) {
        float4 o = make_float4(acc[4 * i + 0], acc[4 * i + 1], acc[4 * i + 2], acc[4 * i + 3]);
        ep[i] = o;
        ap[i] = make_float4(o.x * inv, o.y * inv, o.z * inv, o.w * inv);
    }
}

// ---------------- init ego + all_emb block 0 -----------------------------------
__global__ void init_kernel(const float4* __restrict__ ue, const float4* __restrict__ ie) {
    int i = blockIdx.x * blockDim.x + threadIdx.x;
    int s = gridDim.x * blockDim.x;
    const int tot = NT * 16;
    for (; i < tot; i += s) {
        int row = i >> 4;
        int c = i & 15;
        float4 v = (row < NU) ? ue[i] : ie[i - NU * 16];
        reinterpret_cast<float4*>(g_ego)[i] = v;
        reinterpret_cast<float4*>(g_all)[(size_t)row * 64 + c] = v;
    }
}

// ---------------- final gather: out[12288, 320] --------------------------------
__global__ void gather_kernel(const int* __restrict__ users, const int* __restrict__ pos,
                              const int* __restrict__ neg, float4* __restrict__ out) {
    int r = blockIdx.x;            // 0..12287
    int tid = threadIdx.x;         // 0..95 (80 used)
    if (tid >= 80) return;
    const float4* allp;
    const float4* hp;
    if (r < 4096) {
        int u = __ldg(users + r);
        allp = reinterpret_cast<const float4*>(g_all + (size_t)u * 256);
        hp   = reinterpret_cast<const float4*>(g_uh + (size_t)u * 64);
    } else if (r < 8192) {
        int it = __ldg(pos + (r - 4096));
        allp = reinterpret_cast<const float4*>(g_all + ((size_t)NU + it) * 256);
        hp   = reinterpret_cast<const float4*>(g_ih + (size_t)it * 64);
    } else {
        int it = __ldg(neg + (r - 8192));
        allp = reinterpret_cast<const float4*>(g_all + ((size_t)NU + it) * 256);
        hp   = reinterpret_cast<const float4*>(g_ih + (size_t)it * 64);
    }
    float4 v;
    if (tid < 64) {
        v = allp[tid];
    } else {
        float4 h = hp[tid - 64];
        v = make_float4(fmaxf(h.x, 0.f), fmaxf(h.y, 0.f), fmaxf(h.z, 0.f), fmaxf(h.w, 0.f));
    }
    out[(size_t)r * 80 + tid] = v;
}

// ---------------- host ----------------------------------------------------------
extern "C" void kernel_launch(void* const* d_in, const int* in_sizes, int n_in,
                              void* d_out, int out_size) {
    const int*   users    = (const int*)d_in[0];
    const int*   pos      = (const int*)d_in[1];
    const int*   neg      = (const int*)d_in[2];
    const int*   adj_r    = (const int*)d_in[3];
    const int*   adj_c    = (const int*)d_in[4];
    const float* adj_v    = (const float*)d_in[5];
    const int*   ug_r     = (const int*)d_in[6];
    const int*   ug_c     = (const int*)d_in[7];
    const float* ug_v     = (const float*)d_in[8];
    const int*   ig_r     = (const int*)d_in[9];
    const int*   ig_c     = (const int*)d_in[10];
    const float* ig_v     = (const float*)d_in[11];
    const float* user_emb = (const float*)d_in[12];
    const float* item_emb = (const float*)d_in[13];
    const float* W_gc     = (const float*)d_in[14];
    const float* b_gc     = (const float*)d_in[15];
    const float* W_bi     = (const float*)d_in[16];
    const float* b_bi     = (const float*)d_in[17];
    const float* Wu0      = (const float*)d_in[18];
    const float* bu0      = (const float*)d_in[19];
    const float* Wu1      = (const float*)d_in[20];
    const float* bu1      = (const float*)d_in[21];
    const float* Wi0      = (const float*)d_in[22];
    const float* bi0      = (const float*)d_in[23];
    const float* Wi1      = (const float*)d_in[24];
    const float* bi1      = (const float*)d_in[25];

    const int nnz_adj = in_sizes[3];
    const int nnz_ug  = in_sizes[6];
    const int nnz_ig  = in_sizes[9];

    float *spmm_p, *hid_p, *uh_p, *ih_p;
    cudaGetSymbolAddress((void**)&spmm_p, g_spmm);
    cudaGetSymbolAddress((void**)&hid_p,  g_hid);
    cudaGetSymbolAddress((void**)&uh_p,   g_uh);
    cudaGetSymbolAddress((void**)&ih_p,   g_ih);

    // ---- user MLP path ----
    zero4_kernel<<<1024, 256>>>((float4*)spmm_p, NU * 16);
    spmm_kernel<<<(nnz_ug * 16 + 255) / 256, 256>>>(ug_r, ug_c, ug_v, user_emb, spmm_p, nnz_ug);
    gemm64_kernel<1><<<(NU + 63) / 64, 64>>>(spmm_p, Wu0, bu0, hid_p, NU);
    zero4_kernel<<<1024, 256>>>((float4*)spmm_p, NU * 16);
    spmm_kernel<<<(nnz_ug * 16 + 255) / 256, 256>>>(ug_r, ug_c, ug_v, hid_p, spmm_p, nnz_ug);
    gemm64_kernel<0><<<(NU + 63) / 64, 64>>>(spmm_p, Wu1, bu1, uh_p, NU);

    // ---- item MLP path ----
    zero4_kernel<<<1024, 256>>>((float4*)spmm_p, NI * 16);
    spmm_kernel<<<(nnz_ig * 16 + 255) / 256, 256>>>(ig_r, ig_c, ig_v, item_emb, spmm_p, nnz_ig);
    gemm64_kernel<1><<<(NI + 63) / 64, 64>>>(spmm_p, Wi0, bi0, hid_p, NI);
    zero4_kernel<<<1024, 256>>>((float4*)spmm_p, NI * 16);
    spmm_kernel<<<(nnz_ig * 16 + 255) / 256, 256>>>(ig_r, ig_c, ig_v, hid_p, spmm_p, nnz_ig);
    gemm64_kernel<0><<<(NI + 63) / 64, 64>>>(spmm_p, Wi1, bi1, ih_p, NI);

    // ---- graph conv: ego init + 3 layers ----
    init_kernel<<<1024, 256>>>((const float4*)user_emb, (const float4*)item_emb);
    float* ego_p;
    cudaGetSymbolAddress((void**)&ego_p, g_ego);
    for (int k = 0; k < 3; k++) {
        zero4_kernel<<<2048, 256>>>((float4*)spmm_p, NT * 16);
        spmm_kernel<<<(nnz_adj * 16 + 255) / 256, 256>>>(adj_r, adj_c, adj_v, ego_p, spmm_p, nnz_adj);
        layer_kernel<<<(NT + 63) / 64, 64>>>(W_gc + (size_t)k * 4096, b_gc + (size_t)k * 64,
                                             W_bi + (size_t)k * 4096, b_bi + (size_t)k * 64, k + 1);
    }

    // ---- final gather ----
    gather_kernel<<<12288, 96>>>(users, pos, neg, (float4*)d_out);
}

// round 6
// speedup vs baseline: 1.1156x; 1.1156x over previous
#include <cuda_runtime.h>
#include <math.h>

#define NU 60000
#define NI 120000
#define NT 180000   // NU + NI
#define NNZ_ADJ 3600000
#define NNZ_UG  960000
#define NNZ_IG  1920000

// ---------------- device scratch ------------------------------------------------
__device__ float g_spmm[(size_t)NT * 64];   // spmm output scratch
__device__ float g_hid [(size_t)NI * 64];   // MLP hidden (max of NU/NI rows)
__device__ float g_uh  [(size_t)NU * 64];   // final user MLP output (pre-relu)
__device__ float g_ih  [(size_t)NI * 64];   // final item MLP output (pre-relu)
__device__ float g_ego [(size_t)NT * 64];   // current layer embeddings
__device__ float g_all [(size_t)NT * 256];  // concatenated [ego0 | n1 | n2 | n3]

// CSR storage (built once per call, reused across spmms)
__device__ int   g_adj_col[NNZ_ADJ];
__device__ float g_adj_val[NNZ_ADJ];
__device__ int   g_adj_rp [NT + 1];
__device__ int   g_ug_col [NNZ_UG];
__device__ float g_ug_val [NNZ_UG];
__device__ int   g_ug_rp  [NU + 1];
__device__ int   g_ig_col [NNZ_IG];
__device__ float g_ig_val [NNZ_IG];
__device__ int   g_ig_rp  [NI + 1];
__device__ int   g_counts [NT];
__device__ int   g_off    [NT + 1];

// ---------------- zero ----------------------------------------------------------
__global__ void zero4_kernel(float4* __restrict__ p, int n4) {
    int i = blockIdx.x * blockDim.x + threadIdx.x;
    int s = gridDim.x * blockDim.x;
    float4 z = make_float4(0.f, 0.f, 0.f, 0.f);
    for (; i < n4; i += s) p[i] = z;
}

// ---------------- CSR build: histogram ------------------------------------------
__global__ void hist_kernel(const int* __restrict__ rows, int* __restrict__ counts, int nnz) {
    int i = blockIdx.x * blockDim.x + threadIdx.x;
    int s = gridDim.x * blockDim.x;
    for (; i < nnz; i += s) atomicAdd(counts + __ldg(rows + i), 1);
}

// ---------------- CSR build: single-block exclusive scan ------------------------
__global__ void __launch_bounds__(1024) scan_kernel(
    const int* __restrict__ counts, int* __restrict__ rowptr,
    int* __restrict__ off, int n) {
    __shared__ int warp_sums[32];
    __shared__ int running_s;
    int tid = threadIdx.x;
    int lane = tid & 31, wid = tid >> 5;
    if (tid == 0) running_s = 0;
    __syncthreads();
    for (int base = 0; base < n; base += 1024) {
        int i = base + tid;
        int v = (i < n) ? counts[i] : 0;
        int x = v;
#pragma unroll
        for (int d = 1; d < 32; d <<= 1) {
            int y = __shfl_up_sync(0xffffffffu, x, d);
            if (lane >= d) x += y;
        }
        if (lane == 31) warp_sums[wid] = x;
        __syncthreads();
        if (wid == 0) {
            int s = warp_sums[lane];
#pragma unroll
            for (int d = 1; d < 32; d <<= 1) {
                int y = __shfl_up_sync(0xffffffffu, s, d);
                if (lane >= d) s += y;
            }
            warp_sums[lane] = s;
        }
        __syncthreads();
        int warp_off = (wid > 0) ? warp_sums[wid - 1] : 0;
        int excl = running_s + warp_off + x - v;
        if (i < n) { rowptr[i] = excl; off[i] = excl; }
        __syncthreads();
        if (tid == 1023) running_s += warp_sums[31];
        __syncthreads();
    }
    if (tid == 0) rowptr[n] = running_s;
}

// ---------------- CSR build: scatter --------------------------------------------
__global__ void scatter_kernel(const int* __restrict__ rows, const int* __restrict__ cols,
                               const float* __restrict__ vals, int* __restrict__ off,
                               int* __restrict__ ccol, float* __restrict__ cval, int nnz) {
    int i = blockIdx.x * blockDim.x + threadIdx.x;
    int s = gridDim.x * blockDim.x;
    for (; i < nnz; i += s) {
        int r = __ldg(rows + i);
        int p = atomicAdd(off + r, 1);
        ccol[p] = __ldg(cols + i);
        cval[p] = __ldg(vals + i);
    }
}

// ---------------- CSR SpMM: warp per row, no atomics ----------------------------
__global__ void __launch_bounds__(256) csr_spmm_kernel(
    const int* __restrict__ rowptr, const int* __restrict__ cols,
    const float* __restrict__ vals, const float* __restrict__ x,
    float* __restrict__ out, int nrows) {
    int warp = (blockIdx.x * blockDim.x + threadIdx.x) >> 5;
    int lane = threadIdx.x & 31;
    if (warp >= nrows) return;
    int start = __ldg(rowptr + warp);
    int end   = __ldg(rowptr + warp + 1);
    float a0 = 0.f, a1 = 0.f;
    int fo = lane * 2;
    for (int base = start; base < end; base += 32) {
        int cnt = end - base; if (cnt > 32) cnt = 32;
        int  myc = 0; float myv = 0.f;
        if (base + lane < end) {
            myc = __ldg(cols + base + lane);
            myv = __ldg(vals + base + lane);
        }
#pragma unroll 4
        for (int j = 0; j < cnt; j++) {
            int   c = __shfl_sync(0xffffffffu, myc, j);
            float v = __shfl_sync(0xffffffffu, myv, j);
            float2 xv = *reinterpret_cast<const float2*>(x + (size_t)c * 64 + fo);
            a0 = fmaf(v, xv.x, a0);
            a1 = fmaf(v, xv.y, a1);
        }
    }
    *reinterpret_cast<float2*>(out + (size_t)warp * 64 + fo) = make_float2(a0, a1);
}

// ---------------- GEMM: Y = act(X[R,64] @ W[64,64] + b), row-per-thread --------
template <int ACT>
__global__ void __launch_bounds__(64) gemm64_kernel(
    const float* __restrict__ X, const float* __restrict__ W,
    const float* __restrict__ b, float* __restrict__ Y, int R) {
    __shared__ float Ws[4096];
    __shared__ float xs[4096];
    int tid = threadIdx.x;
    for (int i = tid; i < 4096; i += 64) Ws[i] = W[i];
    int row = blockIdx.x * 64 + tid;
    bool valid = row < R;
    if (valid) {
        const float4* xp = reinterpret_cast<const float4*>(X + (size_t)row * 64);
#pragma unroll
        for (int i = 0; i < 16; i++) {
            float4 t = xp[i];
            xs[(4 * i + 0) * 64 + tid] = t.x;
            xs[(4 * i + 1) * 64 + tid] = t.y;
            xs[(4 * i + 2) * 64 + tid] = t.z;
            xs[(4 * i + 3) * 64 + tid] = t.w;
        }
    }
    __syncthreads();
    if (!valid) return;

    float acc[64];
#pragma unroll
    for (int j = 0; j < 64; j++) acc[j] = __ldg(b + j);

    for (int k = 0; k < 64; k++) {
        float xv = xs[k * 64 + tid];
        const float4* wr = reinterpret_cast<const float4*>(Ws + k * 64);
#pragma unroll
        for (int j = 0; j < 16; j++) {
            float4 w = wr[j];
            acc[4 * j + 0] += xv * w.x;
            acc[4 * j + 1] += xv * w.y;
            acc[4 * j + 2] += xv * w.z;
            acc[4 * j + 3] += xv * w.w;
        }
    }

    float4* yp = reinterpret_cast<float4*>(Y + (size_t)row * 64);
#pragma unroll
    for (int i = 0; i < 16; i++) {
        float a0 = acc[4 * i + 0], a1 = acc[4 * i + 1];
        float a2 = acc[4 * i + 2], a3 = acc[4 * i + 3];
        if (ACT == 1) {
            a0 = a0 > 0.f ? a0 : expm1f(a0);
            a1 = a1 > 0.f ? a1 : expm1f(a1);
            a2 = a2 > 0.f ? a2 : expm1f(a2);
            a3 = a3 > 0.f ? a3 : expm1f(a3);
        }
        yp[i] = make_float4(a0, a1, a2, a3);
    }
}

// ---------------- Fused NGCF layer ----------------------------------------------
__global__ void __launch_bounds__(64) layer_kernel(
    const float* __restrict__ Wg, const float* __restrict__ bg,
    const float* __restrict__ Wb, const float* __restrict__ bb, int kout) {
    __shared__ float Wgs[4096];
    __shared__ float Wbs[4096];
    __shared__ float ss[4096];
    int tid = threadIdx.x;
    for (int i = tid; i < 4096; i += 64) { Wgs[i] = Wg[i]; Wbs[i] = Wb[i]; }
    int row = blockIdx.x * 64 + tid;
    bool valid = row < NT;
    if (valid) {
        const float4* sp = reinterpret_cast<const float4*>(g_spmm + (size_t)row * 64);
#pragma unroll
        for (int i = 0; i < 16; i++) {
            float4 t = sp[i];
            ss[(4 * i + 0) * 64 + tid] = t.x;
            ss[(4 * i + 1) * 64 + tid] = t.y;
            ss[(4 * i + 2) * 64 + tid] = t.z;
            ss[(4 * i + 3) * 64 + tid] = t.w;
        }
    }
    __syncthreads();
    if (!valid) return;

    float acc[64];
#pragma unroll
    for (int j = 0; j < 64; j++) acc[j] = __ldg(bg + j) + __ldg(bb + j);

    const float* erow = g_ego + (size_t)row * 64;
    for (int k = 0; k < 64; k++) {
        float s = ss[k * 64 + tid];
        float p = s * __ldg(erow + k);
        const float4* wg = reinterpret_cast<const float4*>(Wgs + k * 64);
        const float4* wb = reinterpret_cast<const float4*>(Wbs + k * 64);
#pragma unroll
        for (int j = 0; j < 16; j++) {
            float4 a = wg[j];
            float4 c = wb[j];
            acc[4 * j + 0] += s * a.x + p * c.x;
            acc[4 * j + 1] += s * a.y + p * c.y;
            acc[4 * j + 2] += s * a.z + p * c.z;
            acc[4 * j + 3] += s * a.w + p * c.w;
        }
    }

    float ssum = 0.f;
#pragma unroll
    for (int j = 0; j < 64; j++) {
        float v = acc[j];
        v = v >= 0.f ? v : 0.2f * v;
        acc[j] = v;
        ssum += v * v;
    }
    float inv = 1.f / fmaxf(sqrtf(ssum), 1e-12f);

    float4* ep = reinterpret_cast<float4*>(g_ego + (size_t)row * 64);
    float4* ap = reinterpret_cast<float4*>(g_all + (size_t)row * 256 + (size_t)kout * 64);
#pragma unroll
    for (int i = 0; i < 16; i++) {
        float4 o = make_float4(acc[4 * i + 0], acc[4 * i + 1], acc[4 * i + 2], acc[4 * i + 3]);
        ep[i] = o;
        ap[i] = make_float4(o.x * inv, o.y * inv, o.z * inv, o.w * inv);
    }
}

// ---------------- init ego + all_emb block 0 ------------------------------------
__global__ void init_kernel(const float4* __restrict__ ue, const float4* __restrict__ ie) {
    int i = blockIdx.x * blockDim.x + threadIdx.x;
    int s = gridDim.x * blockDim.x;
    const int tot = NT * 16;
    for (; i < tot; i += s) {
        int row = i >> 4;
        int c = i & 15;
        float4 v = (row < NU) ? ue[i] : ie[i - NU * 16];
        reinterpret_cast<float4*>(g_ego)[i] = v;
        reinterpret_cast<float4*>(g_all)[(size_t)row * 64 + c] = v;
    }
}

// ---------------- final gather: out[12288, 320] ---------------------------------
__global__ void gather_kernel(const int* __restrict__ users, const int* __restrict__ pos,
                              const int* __restrict__ neg, float4* __restrict__ out) {
    int r = blockIdx.x;
    int tid = threadIdx.x;
    if (tid >= 80) return;
    const float4* allp;
    const float4* hp;
    if (r < 4096) {
        int u = __ldg(users + r);
        allp = reinterpret_cast<const float4*>(g_all + (size_t)u * 256);
        hp   = reinterpret_cast<const float4*>(g_uh + (size_t)u * 64);
    } else if (r < 8192) {
        int it = __ldg(pos + (r - 4096));
        allp = reinterpret_cast<const float4*>(g_all + ((size_t)NU + it) * 256);
        hp   = reinterpret_cast<const float4*>(g_ih + (size_t)it * 64);
    } else {
        int it = __ldg(neg + (r - 8192));
        allp = reinterpret_cast<const float4*>(g_all + ((size_t)NU + it) * 256);
        hp   = reinterpret_cast<const float4*>(g_ih + (size_t)it * 64);
    }
    float4 v;
    if (tid < 64) {
        v = allp[tid];
    } else {
        float4 h = hp[tid - 64];
        v = make_float4(fmaxf(h.x, 0.f), fmaxf(h.y, 0.f), fmaxf(h.z, 0.f), fmaxf(h.w, 0.f));
    }
    out[(size_t)r * 80 + tid] = v;
}

// ---------------- host ----------------------------------------------------------
static void build_csr(const int* rows, const int* cols, const float* vals, int nnz,
                      int nrows, int* counts, int* off, int* rowptr,
                      int* ccol, float* cval) {
    zero4_kernel<<<512, 256>>>((float4*)counts, nrows / 4);
    hist_kernel<<<2048, 256>>>(rows, counts, nnz);
    scan_kernel<<<1, 1024>>>(counts, rowptr, off, nrows);
    scatter_kernel<<<2048, 256>>>(rows, cols, vals, off, ccol, cval, nnz);
}

extern "C" void kernel_launch(void* const* d_in, const int* in_sizes, int n_in,
                              void* d_out, int out_size) {
    const int*   users    = (const int*)d_in[0];
    const int*   pos      = (const int*)d_in[1];
    const int*   neg      = (const int*)d_in[2];
    const int*   adj_r    = (const int*)d_in[3];
    const int*   adj_c    = (const int*)d_in[4];
    const float* adj_v    = (const float*)d_in[5];
    const int*   ug_r     = (const int*)d_in[6];
    const int*   ug_c     = (const int*)d_in[7];
    const float* ug_v     = (const float*)d_in[8];
    const int*   ig_r     = (const int*)d_in[9];
    const int*   ig_c     = (const int*)d_in[10];
    const float* ig_v     = (const float*)d_in[11];
    const float* user_emb = (const float*)d_in[12];
    const float* item_emb = (const float*)d_in[13];
    const float* W_gc     = (const float*)d_in[14];
    const float* b_gc     = (const float*)d_in[15];
    const float* W_bi     = (const float*)d_in[16];
    const float* b_bi     = (const float*)d_in[17];
    const float* Wu0      = (const float*)d_in[18];
    const float* bu0      = (const float*)d_in[19];
    const float* Wu1      = (const float*)d_in[20];
    const float* bu1      = (const float*)d_in[21];
    const float* Wi0      = (const float*)d_in[22];
    const float* bi0      = (const float*)d_in[23];
    const float* Wi1      = (const float*)d_in[24];
    const float* bi1      = (const float*)d_in[25];

    const int nnz_adj = in_sizes[3];
    const int nnz_ug  = in_sizes[6];
    const int nnz_ig  = in_sizes[9];

    float *spmm_p, *hid_p, *uh_p, *ih_p, *ego_p;
    cudaGetSymbolAddress((void**)&spmm_p, g_spmm);
    cudaGetSymbolAddress((void**)&hid_p,  g_hid);
    cudaGetSymbolAddress((void**)&uh_p,   g_uh);
    cudaGetSymbolAddress((void**)&ih_p,   g_ih);
    cudaGetSymbolAddress((void**)&ego_p,  g_ego);

    int *counts_p, *off_p, *adj_rp, *ug_rp, *ig_rp, *adj_cc, *ug_cc, *ig_cc;
    float *adj_cv, *ug_cv, *ig_cv;
    cudaGetSymbolAddress((void**)&counts_p, g_counts);
    cudaGetSymbolAddress((void**)&off_p,    g_off);
    cudaGetSymbolAddress((void**)&adj_rp,   g_adj_rp);
    cudaGetSymbolAddress((void**)&ug_rp,    g_ug_rp);
    cudaGetSymbolAddress((void**)&ig_rp,    g_ig_rp);
    cudaGetSymbolAddress((void**)&adj_cc,   g_adj_col);
    cudaGetSymbolAddress((void**)&adj_cv,   g_adj_val);
    cudaGetSymbolAddress((void**)&ug_cc,    g_ug_col);
    cudaGetSymbolAddress((void**)&ug_cv,    g_ug_val);
    cudaGetSymbolAddress((void**)&ig_cc,    g_ig_col);
    cudaGetSymbolAddress((void**)&ig_cv,    g_ig_val);

    // ---- build CSR for all three sparse matrices ----
    build_csr(ug_r,  ug_c,  ug_v,  nnz_ug,  NU, counts_p, off_p, ug_rp,  ug_cc,  ug_cv);
    build_csr(ig_r,  ig_c,  ig_v,  nnz_ig,  NI, counts_p, off_p, ig_rp,  ig_cc,  ig_cv);
    build_csr(adj_r, adj_c, adj_v, nnz_adj, NT, counts_p, off_p, adj_rp, adj_cc, adj_cv);

    // ---- user MLP path ----
    csr_spmm_kernel<<<(NU + 7) / 8, 256>>>(ug_rp, ug_cc, ug_cv, user_emb, spmm_p, NU);
    gemm64_kernel<1><<<(NU + 63) / 64, 64>>>(spmm_p, Wu0, bu0, hid_p, NU);
    csr_spmm_kernel<<<(NU + 7) / 8, 256>>>(ug_rp, ug_cc, ug_cv, hid_p, spmm_p, NU);
    gemm64_kernel<0><<<(NU + 63) / 64, 64>>>(spmm_p, Wu1, bu1, uh_p, NU);

    // ---- item MLP path ----
    csr_spmm_kernel<<<(NI + 7) / 8, 256>>>(ig_rp, ig_cc, ig_cv, item_emb, spmm_p, NI);
    gemm64_kernel<1><<<(NI + 63) / 64, 64>>>(spmm_p, Wi0, bi0, hid_p, NI);
    csr_spmm_kernel<<<(NI + 7) / 8, 256>>>(ig_rp, ig_cc, ig_cv, hid_p, spmm_p, NI);
    gemm64_kernel<0><<<(NI + 63) / 64, 64>>>(spmm_p, Wi1, bi1, ih_p, NI);

    // ---- graph conv: ego init + 3 layers ----
    init_kernel<<<1024, 256>>>((const float4*)user_emb, (const float4*)item_emb);
    for (int k = 0; k < 3; k++) {
        csr_spmm_kernel<<<(NT + 7) / 8, 256>>>(adj_rp, adj_cc, adj_cv, ego_p, spmm_p, NT);
        layer_kernel<<<(NT + 63) / 64, 64>>>(W_gc + (size_t)k * 4096, b_gc + (size_t)k * 64,
                                             W_bi + (size_t)k * 4096, b_bi + (size_t)k * 64, k + 1);
    }

    // ---- final gather ----
    gather_kernel<<<12288, 96>>>(users, pos, neg, (float4*)d_out);
}

// round 7
// speedup vs baseline: 1.3847x; 1.2412x over previous
#include <cuda_runtime.h>
#include <math.h>

#define NU 60000
#define NI 120000
#define NT 180000   // NU + NI
#define NNZ_ADJ 3600000
#define NNZ_UG  960000
#define NNZ_IG  1920000

// ---------------- device scratch ------------------------------------------------
__device__ float g_spmm  [(size_t)NT * 64];  // conv-path spmm output
__device__ float g_spmm_u[(size_t)NU * 64];  // user-path spmm output
__device__ float g_spmm_i[(size_t)NI * 64];  // item-path spmm output
__device__ float g_hid_u [(size_t)NU * 64];  // user MLP hidden
__device__ float g_hid_i [(size_t)NI * 64];  // item MLP hidden
__device__ float g_uh    [(size_t)NU * 64];  // user MLP out (pre-relu)
__device__ float g_ih    [(size_t)NI * 64];  // item MLP out (pre-relu)
__device__ float g_ego   [(size_t)NT * 64];  // current layer embeddings
__device__ float g_all   [(size_t)NT * 256]; // [ego0 | n1 | n2 | n3]

// CSR storage
__device__ int   g_adj_col[NNZ_ADJ];
__device__ float g_adj_val[NNZ_ADJ];
__device__ int   g_adj_rp [NT + 1];
__device__ int   g_ug_col [NNZ_UG];
__device__ float g_ug_val [NNZ_UG];
__device__ int   g_ug_rp  [NU + 1];
__device__ int   g_ig_col [NNZ_IG];
__device__ float g_ig_val [NNZ_IG];
__device__ int   g_ig_rp  [NI + 1];
// per-branch build scratch (branches run concurrently -> no sharing)
__device__ int   g_counts_a[NT];
__device__ int   g_counts_u[NU];
__device__ int   g_counts_i[NI];
__device__ int   g_off_a   [NT];
__device__ int   g_off_u   [NU];
__device__ int   g_off_i   [NI];
__device__ int   g_bsums_a [256];
__device__ int   g_bsums_u [256];
__device__ int   g_bsums_i [256];

// ---------------- zero ----------------------------------------------------------
__global__ void zero4_kernel(float4* __restrict__ p, int n4) {
    int i = blockIdx.x * blockDim.x + threadIdx.x;
    int s = gridDim.x * blockDim.x;
    float4 z = make_float4(0.f, 0.f, 0.f, 0.f);
    for (; i < n4; i += s) p[i] = z;
}

// ---------------- CSR build: histogram ------------------------------------------
__global__ void hist_kernel(const int* __restrict__ rows, int* __restrict__ counts, int nnz) {
    int i = blockIdx.x * blockDim.x + threadIdx.x;
    int s = gridDim.x * blockDim.x;
    for (; i < nnz; i += s) atomicAdd(counts + __ldg(rows + i), 1);
}

// ---------------- two-level scan -------------------------------------------------
__global__ void __launch_bounds__(1024) scan_local_kernel(
    const int* __restrict__ counts, int* __restrict__ rowptr,
    int* __restrict__ bsums, int n) {
    __shared__ int ws[32];
    int tid = threadIdx.x, lane = tid & 31, w = tid >> 5;
    int i = blockIdx.x * 1024 + tid;
    int v = (i < n) ? counts[i] : 0;
    int x = v;
#pragma unroll
    for (int d = 1; d < 32; d <<= 1) {
        int y = __shfl_up_sync(0xffffffffu, x, d);
        if (lane >= d) x += y;
    }
    if (lane == 31) ws[w] = x;
    __syncthreads();
    if (w == 0) {
        int s = ws[lane];
#pragma unroll
        for (int d = 1; d < 32; d <<= 1) {
            int y = __shfl_up_sync(0xffffffffu, s, d);
            if (lane >= d) s += y;
        }
        ws[lane] = s;
    }
    __syncthreads();
    int excl = x - v + (w > 0 ? ws[w - 1] : 0);
    if (i < n) rowptr[i] = excl;
    if (tid == 1023) bsums[blockIdx.x] = excl + v;
}

__global__ void __launch_bounds__(256) scan_bsums_kernel(int* __restrict__ bsums, int nb) {
    __shared__ int ws[8];
    int tid = threadIdx.x, lane = tid & 31, w = tid >> 5;
    int v = (tid < nb) ? bsums[tid] : 0;
    int x = v;
#pragma unroll
    for (int d = 1; d < 32; d <<= 1) {
        int y = __shfl_up_sync(0xffffffffu, x, d);
        if (lane >= d) x += y;
    }
    if (lane == 31) ws[w] = x;
    __syncthreads();
    if (w == 0) {
        int s = (lane < 8) ? ws[lane] : 0;
#pragma unroll
        for (int d = 1; d < 8; d <<= 1) {
            int y = __shfl_up_sync(0xffffffffu, s, d);
            if (lane >= d) s += y;
        }
        if (lane < 8) ws[lane] = s;
    }
    __syncthreads();
    int excl = x - v + (w > 0 ? ws[w - 1] : 0);
    __syncthreads();
    if (tid < nb) bsums[tid] = excl;
}

__global__ void scan_add_kernel(int* __restrict__ rowptr, int* __restrict__ off,
                                const int* __restrict__ bsums, int n, int nnz) {
    int i = blockIdx.x * blockDim.x + threadIdx.x;
    if (i < n) {
        int v = rowptr[i] + __ldg(bsums + (i >> 10));
        rowptr[i] = v;
        off[i] = v;
    }
    if (i == 0) rowptr[n] = nnz;
}

// ---------------- CSR build: scatter --------------------------------------------
__global__ void scatter_kernel(const int* __restrict__ rows, const int* __restrict__ cols,
                               const float* __restrict__ vals, int* __restrict__ off,
                               int* __restrict__ ccol, float* __restrict__ cval, int nnz) {
    int i = blockIdx.x * blockDim.x + threadIdx.x;
    int s = gridDim.x * blockDim.x;
    for (; i < nnz; i += s) {
        int r = __ldg(rows + i);
        int p = atomicAdd(off + r, 1);
        ccol[p] = __ldg(cols + i);
        cval[p] = __ldg(vals + i);
    }
}

// ---------------- CSR SpMM: warp per row ----------------------------------------
__global__ void __launch_bounds__(256) csr_spmm_kernel(
    const int* __restrict__ rowptr, const int* __restrict__ cols,
    const float* __restrict__ vals, const float* __restrict__ x,
    float* __restrict__ out, int nrows) {
    int warp = (blockIdx.x * blockDim.x + threadIdx.x) >> 5;
    int lane = threadIdx.x & 31;
    if (warp >= nrows) return;
    int start = __ldg(rowptr + warp);
    int end   = __ldg(rowptr + warp + 1);
    float a0 = 0.f, a1 = 0.f;
    int fo = lane * 2;
    for (int base = start; base < end; base += 32) {
        int cnt = end - base; if (cnt > 32) cnt = 32;
        int  myc = 0; float myv = 0.f;
        if (base + lane < end) {
            myc = __ldg(cols + base + lane);
            myv = __ldg(vals + base + lane);
        }
#pragma unroll 4
        for (int j = 0; j < cnt; j++) {
            int   c = __shfl_sync(0xffffffffu, myc, j);
            float v = __shfl_sync(0xffffffffu, myv, j);
            float2 xv = *reinterpret_cast<const float2*>(x + (size_t)c * 64 + fo);
            a0 = fmaf(v, xv.x, a0);
            a1 = fmaf(v, xv.y, a1);
        }
    }
    *reinterpret_cast<float2*>(out + (size_t)warp * 64 + fo) = make_float2(a0, a1);
}

// ---------------- GEMM: Y = act(X[R,64] @ W[64,64] + b) -------------------------
template <int ACT>
__global__ void __launch_bounds__(64) gemm64_kernel(
    const float* __restrict__ X, const float* __restrict__ W,
    const float* __restrict__ b, float* __restrict__ Y, int R) {
    __shared__ float Ws[4096];
    __shared__ float xs[4096];
    int tid = threadIdx.x;
    for (int i = tid; i < 4096; i += 64) Ws[i] = W[i];
    int row = blockIdx.x * 64 + tid;
    bool valid = row < R;
    if (valid) {
        const float4* xp = reinterpret_cast<const float4*>(X + (size_t)row * 64);
#pragma unroll
        for (int i = 0; i < 16; i++) {
            float4 t = xp[i];
            xs[(4 * i + 0) * 64 + tid] = t.x;
            xs[(4 * i + 1) * 64 + tid] = t.y;
            xs[(4 * i + 2) * 64 + tid] = t.z;
            xs[(4 * i + 3) * 64 + tid] = t.w;
        }
    }
    __syncthreads();
    if (!valid) return;

    float acc[64];
#pragma unroll
    for (int j = 0; j < 64; j++) acc[j] = __ldg(b + j);

    for (int k = 0; k < 64; k++) {
        float xv = xs[k * 64 + tid];
        const float4* wr = reinterpret_cast<const float4*>(Ws + k * 64);
#pragma unroll
        for (int j = 0; j < 16; j++) {
            float4 w = wr[j];
            acc[4 * j + 0] += xv * w.x;
            acc[4 * j + 1] += xv * w.y;
            acc[4 * j + 2] += xv * w.z;
            acc[4 * j + 3] += xv * w.w;
        }
    }

    float4* yp = reinterpret_cast<float4*>(Y + (size_t)row * 64);
#pragma unroll
    for (int i = 0; i < 16; i++) {
        float a0 = acc[4 * i + 0], a1 = acc[4 * i + 1];
        float a2 = acc[4 * i + 2], a3 = acc[4 * i + 3];
        if (ACT == 1) {
            a0 = a0 > 0.f ? a0 : expm1f(a0);
            a1 = a1 > 0.f ? a1 : expm1f(a1);
            a2 = a2 > 0.f ? a2 : expm1f(a2);
            a3 = a3 > 0.f ? a3 : expm1f(a3);
        }
        yp[i] = make_float4(a0, a1, a2, a3);
    }
}

// ---------------- Fused NGCF layer ----------------------------------------------
__global__ void __launch_bounds__(64) layer_kernel(
    const float* __restrict__ Wg, const float* __restrict__ bg,
    const float* __restrict__ Wb, const float* __restrict__ bb, int kout) {
    __shared__ float Wgs[4096];
    __shared__ float Wbs[4096];
    __shared__ float ss[4096];
    int tid = threadIdx.x;
    for (int i = tid; i < 4096; i += 64) { Wgs[i] = Wg[i]; Wbs[i] = Wb[i]; }
    int row = blockIdx.x * 64 + tid;
    bool valid = row < NT;
    if (valid) {
        const float4* sp = reinterpret_cast<const float4*>(g_spmm + (size_t)row * 64);
#pragma unroll
        for (int i = 0; i < 16; i++) {
            float4 t = sp[i];
            ss[(4 * i + 0) * 64 + tid] = t.x;
            ss[(4 * i + 1) * 64 + tid] = t.y;
            ss[(4 * i + 2) * 64 + tid] = t.z;
            ss[(4 * i + 3) * 64 + tid] = t.w;
        }
    }
    __syncthreads();
    if (!valid) return;

    float acc[64];
#pragma unroll
    for (int j = 0; j < 64; j++) acc[j] = __ldg(bg + j) + __ldg(bb + j);

    const float* erow = g_ego + (size_t)row * 64;
    for (int k = 0; k < 64; k++) {
        float s = ss[k * 64 + tid];
        float p = s * __ldg(erow + k);
        const float4* wg = reinterpret_cast<const float4*>(Wgs + k * 64);
        const float4* wb = reinterpret_cast<const float4*>(Wbs + k * 64);
#pragma unroll
        for (int j = 0; j < 16; j++) {
            float4 a = wg[j];
            float4 c = wb[j];
            acc[4 * j + 0] += s * a.x + p * c.x;
            acc[4 * j + 1] += s * a.y + p * c.y;
            acc[4 * j + 2] += s * a.z + p * c.z;
            acc[4 * j + 3] += s * a.w + p * c.w;
        }
    }

    float ssum = 0.f;
#pragma unroll
    for (int j = 0; j < 64; j++) {
        float v = acc[j];
        v = v >= 0.f ? v : 0.2f * v;
        acc[j] = v;
        ssum += v * v;
    }
    float inv = 1.f / fmaxf(sqrtf(ssum), 1e-12f);

    float4* ep = reinterpret_cast<float4*>(g_ego + (size_t)row * 64);
    float4* ap = reinterpret_cast<float4*>(g_all + (size_t)row * 256 + (size_t)kout * 64);
#pragma unroll
    for (int i = 0; i < 16; i++) {
        float4 o = make_float4(acc[4 * i + 0], acc[4 * i + 1], acc[4 * i + 2], acc[4 * i + 3]);
        ep[i] = o;
        ap[i] = make_float4(o.x * inv, o.y * inv, o.z * inv, o.w * inv);
    }
}

// ---------------- init ego + all_emb block 0 ------------------------------------
__global__ void init_kernel(const float4* __restrict__ ue, const float4* __restrict__ ie) {
    int i = blockIdx.x * blockDim.x + threadIdx.x;
    int s = gridDim.x * blockDim.x;
    const int tot = NT * 16;
    for (; i < tot; i += s) {
        int row = i >> 4;
        int c = i & 15;
        float4 v = (row < NU) ? ue[i] : ie[i - NU * 16];
        reinterpret_cast<float4*>(g_ego)[i] = v;
        reinterpret_cast<float4*>(g_all)[(size_t)row * 64 + c] = v;
    }
}

// ---------------- final gather: out[12288, 320] ---------------------------------
__global__ void gather_kernel(const int* __restrict__ users, const int* __restrict__ pos,
                              const int* __restrict__ neg, float4* __restrict__ out) {
    int r = blockIdx.x;
    int tid = threadIdx.x;
    if (tid >= 80) return;
    const float4* allp;
    const float4* hp;
    if (r < 4096) {
        int u = __ldg(users + r);
        allp = reinterpret_cast<const float4*>(g_all + (size_t)u * 256);
        hp   = reinterpret_cast<const float4*>(g_uh + (size_t)u * 64);
    } else if (r < 8192) {
        int it = __ldg(pos + (r - 4096));
        allp = reinterpret_cast<const float4*>(g_all + ((size_t)NU + it) * 256);
        hp   = reinterpret_cast<const float4*>(g_ih + (size_t)it * 64);
    } else {
        int it = __ldg(neg + (r - 8192));
        allp = reinterpret_cast<const float4*>(g_all + ((size_t)NU + it) * 256);
        hp   = reinterpret_cast<const float4*>(g_ih + (size_t)it * 64);
    }
    float4 v;
    if (tid < 64) {
        v = allp[tid];
    } else {
        float4 h = hp[tid - 64];
        v = make_float4(fmaxf(h.x, 0.f), fmaxf(h.y, 0.f), fmaxf(h.z, 0.f), fmaxf(h.w, 0.f));
    }
    out[(size_t)r * 80 + tid] = v;
}

// ---------------- host ----------------------------------------------------------
static void build_csr(cudaStream_t st, const int* rows, const int* cols, const float* vals,
                      int nnz, int nrows, int* counts, int* off, int* rowptr,
                      int* bsums, int* ccol, float* cval) {
    zero4_kernel<<<256, 256, 0, st>>>((float4*)counts, nrows / 4);
    hist_kernel<<<2048, 256, 0, st>>>(rows, counts, nnz);
    int nb = (nrows + 1023) / 1024;
    scan_local_kernel<<<nb, 1024, 0, st>>>(counts, rowptr, bsums, nrows);
    scan_bsums_kernel<<<1, 256, 0, st>>>(bsums, nb);
    scan_add_kernel<<<nb, 1024, 0, st>>>(rowptr, off, bsums, nrows, nnz);
    scatter_kernel<<<2048, 256, 0, st>>>(rows, cols, vals, off, ccol, cval, nnz);
}

extern "C" void kernel_launch(void* const* d_in, const int* in_sizes, int n_in,
                              void* d_out, int out_size) {
    const int*   users    = (const int*)d_in[0];
    const int*   pos      = (const int*)d_in[1];
    const int*   neg      = (const int*)d_in[2];
    const int*   adj_r    = (const int*)d_in[3];
    const int*   adj_c    = (const int*)d_in[4];
    const float* adj_v    = (const float*)d_in[5];
    const int*   ug_r     = (const int*)d_in[6];
    const int*   ug_c     = (const int*)d_in[7];
    const float* ug_v     = (const float*)d_in[8];
    const int*   ig_r     = (const int*)d_in[9];
    const int*   ig_c     = (const int*)d_in[10];
    const float* ig_v     = (const float*)d_in[11];
    const float* user_emb = (const float*)d_in[12];
    const float* item_emb = (const float*)d_in[13];
    const float* W_gc     = (const float*)d_in[14];
    const float* b_gc     = (const float*)d_in[15];
    const float* W_bi     = (const float*)d_in[16];
    const float* b_bi     = (const float*)d_in[17];
    const float* Wu0      = (const float*)d_in[18];
    const float* bu0      = (const float*)d_in[19];
    const float* Wu1      = (const float*)d_in[20];
    const float* bu1      = (const float*)d_in[21];
    const float* Wi0      = (const float*)d_in[22];
    const float* bi0      = (const float*)d_in[23];
    const float* Wi1      = (const float*)d_in[24];
    const float* bi1      = (const float*)d_in[25];

    const int nnz_adj = in_sizes[3];
    const int nnz_ug  = in_sizes[6];
    const int nnz_ig  = in_sizes[9];

    // one-time host resources (created on the uncaptured correctness call)
    static cudaStream_t s1 = nullptr, s2 = nullptr;
    static cudaEvent_t evR = nullptr, ev1 = nullptr, ev2 = nullptr;
    if (s1 == nullptr) {
        cudaStreamCreateWithFlags(&s1, cudaStreamNonBlocking);
        cudaStreamCreateWithFlags(&s2, cudaStreamNonBlocking);
        cudaEventCreateWithFlags(&evR, cudaEventDisableTiming);
        cudaEventCreateWithFlags(&ev1, cudaEventDisableTiming);
        cudaEventCreateWithFlags(&ev2, cudaEventDisableTiming);
    }

    float *spmm_p, *spmm_u, *spmm_i, *hid_u, *hid_i, *uh_p, *ih_p, *ego_p;
    cudaGetSymbolAddress((void**)&spmm_p, g_spmm);
    cudaGetSymbolAddress((void**)&spmm_u, g_spmm_u);
    cudaGetSymbolAddress((void**)&spmm_i, g_spmm_i);
    cudaGetSymbolAddress((void**)&hid_u,  g_hid_u);
    cudaGetSymbolAddress((void**)&hid_i,  g_hid_i);
    cudaGetSymbolAddress((void**)&uh_p,   g_uh);
    cudaGetSymbolAddress((void**)&ih_p,   g_ih);
    cudaGetSymbolAddress((void**)&ego_p,  g_ego);

    int *cnt_a, *cnt_u, *cnt_i, *off_a, *off_u, *off_i, *bs_a, *bs_u, *bs_i;
    int *adj_rp, *ug_rp, *ig_rp, *adj_cc, *ug_cc, *ig_cc;
    float *adj_cv, *ug_cv, *ig_cv;
    cudaGetSymbolAddress((void**)&cnt_a, g_counts_a);
    cudaGetSymbolAddress((void**)&cnt_u, g_counts_u);
    cudaGetSymbolAddress((void**)&cnt_i, g_counts_i);
    cudaGetSymbolAddress((void**)&off_a, g_off_a);
    cudaGetSymbolAddress((void**)&off_u, g_off_u);
    cudaGetSymbolAddress((void**)&off_i, g_off_i);
    cudaGetSymbolAddress((void**)&bs_a,  g_bsums_a);
    cudaGetSymbolAddress((void**)&bs_u,  g_bsums_u);
    cudaGetSymbolAddress((void**)&bs_i,  g_bsums_i);
    cudaGetSymbolAddress((void**)&adj_rp, g_adj_rp);
    cudaGetSymbolAddress((void**)&ug_rp,  g_ug_rp);
    cudaGetSymbolAddress((void**)&ig_rp,  g_ig_rp);
    cudaGetSymbolAddress((void**)&adj_cc, g_adj_col);
    cudaGetSymbolAddress((void**)&adj_cv, g_adj_val);
    cudaGetSymbolAddress((void**)&ug_cc,  g_ug_col);
    cudaGetSymbolAddress((void**)&ug_cv,  g_ug_val);
    cudaGetSymbolAddress((void**)&ig_cc,  g_ig_col);
    cudaGetSymbolAddress((void**)&ig_cv,  g_ig_val);

    // ---- fork: side branches wait on root event ----
    cudaEventRecord(evR, 0);
    cudaStreamWaitEvent(s1, evR, 0);
    cudaStreamWaitEvent(s2, evR, 0);

    // ---- branch 1 (s1): user MLP path ----
    build_csr(s1, ug_r, ug_c, ug_v, nnz_ug, NU, cnt_u, off_u, ug_rp, bs_u, ug_cc, ug_cv);
    csr_spmm_kernel<<<(NU + 7) / 8, 256, 0, s1>>>(ug_rp, ug_cc, ug_cv, user_emb, spmm_u, NU);
    gemm64_kernel<1><<<(NU + 63) / 64, 64, 0, s1>>>(spmm_u, Wu0, bu0, hid_u, NU);
    csr_spmm_kernel<<<(NU + 7) / 8, 256, 0, s1>>>(ug_rp, ug_cc, ug_cv, hid_u, spmm_u, NU);
    gemm64_kernel<0><<<(NU + 63) / 64, 64, 0, s1>>>(spmm_u, Wu1, bu1, uh_p, NU);
    cudaEventRecord(ev1, s1);

    // ---- branch 2 (s2): item MLP path ----
    build_csr(s2, ig_r, ig_c, ig_v, nnz_ig, NI, cnt_i, off_i, ig_rp, bs_i, ig_cc, ig_cv);
    csr_spmm_kernel<<<(NI + 7) / 8, 256, 0, s2>>>(ig_rp, ig_cc, ig_cv, item_emb, spmm_i, NI);
    gemm64_kernel<1><<<(NI + 63) / 64, 64, 0, s2>>>(spmm_i, Wi0, bi0, hid_i, NI);
    csr_spmm_kernel<<<(NI + 7) / 8, 256, 0, s2>>>(ig_rp, ig_cc, ig_cv, hid_i, spmm_i, NI);
    gemm64_kernel<0><<<(NI + 63) / 64, 64, 0, s2>>>(spmm_i, Wi1, bi1, ih_p, NI);
    cudaEventRecord(ev2, s2);

    // ---- main stream: graph conv path (critical) ----
    init_kernel<<<1024, 256>>>((const float4*)user_emb, (const float4*)item_emb);
    build_csr(0, adj_r, adj_c, adj_v, nnz_adj, NT, cnt_a, off_a, adj_rp, bs_a, adj_cc, adj_cv);
    for (int k = 0; k < 3; k++) {
        csr_spmm_kernel<<<(NT + 7) / 8, 256>>>(adj_rp, adj_cc, adj_cv, ego_p, spmm_p, NT);
        layer_kernel<<<(NT + 63) / 64, 64>>>(W_gc + (size_t)k * 4096, b_gc + (size_t)k * 64,
                                             W_bi + (size_t)k * 4096, b_bi + (size_t)k * 64, k + 1);
    }

    // ---- join + final gather ----
    cudaStreamWaitEvent(0, ev1, 0);
    cudaStreamWaitEvent(0, ev2, 0);
    gather_kernel<<<12288, 96>>>(users, pos, neg, (float4*)d_out);
}

// round 10
// speedup vs baseline: 1.5910x; 1.1490x over previous
#include <cuda_runtime.h>
#include <math.h>

#define NU 60000
#define NI 120000
#define NT 180000   // NU + NI
#define NNZ_ADJ 3600000
#define NNZ_UG  960000
#define NNZ_IG  1920000

// ---------------- device scratch ------------------------------------------------
__device__ float g_spmm  [(size_t)NT * 64];  // conv-path spmm output
__device__ float g_spmm_u[(size_t)NU * 64];  // user-path spmm output
__device__ float g_spmm_i[(size_t)NI * 64];  // item-path spmm output
__device__ float g_hid_u [(size_t)NU * 64];  // user MLP hidden
__device__ float g_hid_i [(size_t)NI * 64];  // item MLP hidden
__device__ float g_uh    [(size_t)NU * 64];  // user MLP out (pre-relu)
__device__ float g_ih    [(size_t)NI * 64];  // item MLP out (pre-relu)
__device__ float g_ego   [(size_t)NT * 64];  // current layer embeddings (written by layer 1)
__device__ float g_all   [(size_t)NT * 256]; // [ego0 | n1 | n2 | n3]

// CSR storage
__device__ int   g_adj_col[NNZ_ADJ];
__device__ float g_adj_val[NNZ_ADJ];
__device__ int   g_adj_rp [NT + 1];
__device__ int   g_ug_col [NNZ_UG];
__device__ float g_ug_val [NNZ_UG];
__device__ int   g_ug_rp  [NU + 1];
__device__ int   g_ig_col [NNZ_IG];
__device__ float g_ig_val [NNZ_IG];
__device__ int   g_ig_rp  [NI + 1];
// per-branch build scratch
__device__ int   g_counts_a[NT];
__device__ int   g_counts_u[NU];
__device__ int   g_counts_i[NI];
__device__ int   g_off_a   [NT];
__device__ int   g_off_u   [NU];
__device__ int   g_off_i   [NI];
__device__ int   g_bsums_a [256];
__device__ int   g_bsums_u [256];
__device__ int   g_bsums_i [256];

// ---------------- zero ----------------------------------------------------------
__global__ void zero4_kernel(float4* __restrict__ p, int n4) {
    int i = blockIdx.x * blockDim.x + threadIdx.x;
    int s = gridDim.x * blockDim.x;
    float4 z = make_float4(0.f, 0.f, 0.f, 0.f);
    for (; i < n4; i += s) p[i] = z;
}

// ---------------- CSR build: histogram ------------------------------------------
__global__ void hist_kernel(const int* __restrict__ rows, int* __restrict__ counts, int nnz) {
    int i = blockIdx.x * blockDim.x + threadIdx.x;
    int s = gridDim.x * blockDim.x;
    for (; i < nnz; i += s) atomicAdd(counts + __ldg(rows + i), 1);
}

// ---------------- two-level scan -------------------------------------------------
__global__ void __launch_bounds__(1024) scan_local_kernel(
    const int* __restrict__ counts, int* __restrict__ rowptr,
    int* __restrict__ bsums, int n) {
    __shared__ int ws[32];
    int tid = threadIdx.x, lane = tid & 31, w = tid >> 5;
    int i = blockIdx.x * 1024 + tid;
    int v = (i < n) ? counts[i] : 0;
    int x = v;
#pragma unroll
    for (int d = 1; d < 32; d <<= 1) {
        int y = __shfl_up_sync(0xffffffffu, x, d);
        if (lane >= d) x += y;
    }
    if (lane == 31) ws[w] = x;
    __syncthreads();
    if (w == 0) {
        int s = ws[lane];
#pragma unroll
        for (int d = 1; d < 32; d <<= 1) {
            int y = __shfl_up_sync(0xffffffffu, s, d);
            if (lane >= d) s += y;
        }
        ws[lane] = s;
    }
    __syncthreads();
    int excl = x - v + (w > 0 ? ws[w - 1] : 0);
    if (i < n) rowptr[i] = excl;
    if (tid == 1023) bsums[blockIdx.x] = excl + v;
}

__global__ void __launch_bounds__(256) scan_bsums_kernel(int* __restrict__ bsums, int nb) {
    __shared__ int ws[8];
    int tid = threadIdx.x, lane = tid & 31, w = tid >> 5;
    int v = (tid < nb) ? bsums[tid] : 0;
    int x = v;
#pragma unroll
    for (int d = 1; d < 32; d <<= 1) {
        int y = __shfl_up_sync(0xffffffffu, x, d);
        if (lane >= d) x += y;
    }
    if (lane == 31) ws[w] = x;
    __syncthreads();
    if (w == 0) {
        int s = (lane < 8) ? ws[lane] : 0;
#pragma unroll
        for (int d = 1; d < 8; d <<= 1) {
            int y = __shfl_up_sync(0xffffffffu, s, d);
            if (lane >= d) s += y;
        }
        if (lane < 8) ws[lane] = s;
    }
    __syncthreads();
    int excl = x - v + (w > 0 ? ws[w - 1] : 0);
    __syncthreads();
    if (tid < nb) bsums[tid] = excl;
}

__global__ void scan_add_kernel(int* __restrict__ rowptr, int* __restrict__ off,
                                const int* __restrict__ bsums, int n, int nnz) {
    int i = blockIdx.x * blockDim.x + threadIdx.x;
    if (i < n) {
        int v = rowptr[i] + __ldg(bsums + (i >> 10));
        rowptr[i] = v;
        off[i] = v;
    }
    if (i == 0) rowptr[n] = nnz;
}

// ---------------- CSR build: scatter --------------------------------------------
__global__ void scatter_kernel(const int* __restrict__ rows, const int* __restrict__ cols,
                               const float* __restrict__ vals, int* __restrict__ off,
                               int* __restrict__ ccol, float* __restrict__ cval, int nnz) {
    int i = blockIdx.x * blockDim.x + threadIdx.x;
    int s = gridDim.x * blockDim.x;
    for (; i < nnz; i += s) {
        int r = __ldg(rows + i);
        int p = atomicAdd(off + r, 1);
        ccol[p] = __ldg(cols + i);
        cval[p] = __ldg(vals + i);
    }
}

// ---------------- CSR SpMM: 4 rows per warp, 8 lanes per row, no shfl -----------
// SPLIT: x is the concatenated [user_emb ; item_emb] view (col < NU -> xu, else xi)
template <bool SPLIT>
__global__ void __launch_bounds__(256) csr_spmm4_kernel(
    const int* __restrict__ rowptr, const int* __restrict__ cols,
    const float* __restrict__ vals, const float* __restrict__ xu,
    const float* __restrict__ xi, float* __restrict__ out, int nrows) {
    int warp = (blockIdx.x * blockDim.x + threadIdx.x) >> 5;
    int lane = threadIdx.x & 31;
    int g    = lane >> 3;         // row group 0..3
    int sub  = lane & 7;          // 8 floats each: [sub*8, sub*8+8)
    int row  = warp * 4 + g;
    bool valid = row < nrows;
    int start = valid ? __ldg(rowptr + row)     : 0;
    int end   = valid ? __ldg(rowptr + row + 1) : 0;

    float4 a0 = make_float4(0.f, 0.f, 0.f, 0.f);
    float4 a1 = make_float4(0.f, 0.f, 0.f, 0.f);

    for (int j = start; j < end; j++) {
        int   c = __ldg(cols + j);   // 8-way broadcast within group
        float v = __ldg(vals + j);
        const float* xr;
        if (SPLIT) {
            xr = (c < NU) ? (xu + (size_t)c * 64) : (xi + (size_t)(c - NU) * 64);
        } else {
            xr = xu + (size_t)c * 64;
        }
        float4 xa = __ldg(reinterpret_cast<const float4*>(xr + sub * 8));
        float4 xb = __ldg(reinterpret_cast<const float4*>(xr + sub * 8 + 4));
        a0.x = fmaf(v, xa.x, a0.x); a0.y = fmaf(v, xa.y, a0.y);
        a0.z = fmaf(v, xa.z, a0.z); a0.w = fmaf(v, xa.w, a0.w);
        a1.x = fmaf(v, xb.x, a1.x); a1.y = fmaf(v, xb.y, a1.y);
        a1.z = fmaf(v, xb.z, a1.z); a1.w = fmaf(v, xb.w, a1.w);
    }
    if (valid) {
        float4* op = reinterpret_cast<float4*>(out + (size_t)row * 64 + sub * 8);
        op[0] = a0;
        op[1] = a1;
    }
}

// ---------------- GEMM: Y = act(X[R,64] @ W[64,64] + b), 128 thr, dyn smem -----
template <int ACT>
__global__ void __launch_bounds__(128) gemm64_kernel(
    const float* __restrict__ X, const float* __restrict__ W,
    const float* __restrict__ b, float* __restrict__ Y, int R) {
    extern __shared__ float sm[];
    float* Ws = sm;           // 4096
    float* xs = sm + 4096;    // 8192 (transposed [k][tid])
    int tid = threadIdx.x;
    for (int i = tid; i < 4096; i += 128) Ws[i] = W[i];
    int row = blockIdx.x * 128 + tid;
    bool valid = row < R;
    if (valid) {
        const float4* xp = reinterpret_cast<const float4*>(X + (size_t)row * 64);
#pragma unroll
        for (int i = 0; i < 16; i++) {
            float4 t = xp[i];
            xs[(4 * i + 0) * 128 + tid] = t.x;
            xs[(4 * i + 1) * 128 + tid] = t.y;
            xs[(4 * i + 2) * 128 + tid] = t.z;
            xs[(4 * i + 3) * 128 + tid] = t.w;
        }
    }
    __syncthreads();
    if (!valid) return;

    float acc[64];
#pragma unroll
    for (int j = 0; j < 64; j++) acc[j] = __ldg(b + j);

    for (int k = 0; k < 64; k++) {
        float xv = xs[k * 128 + tid];
        const float4* wr = reinterpret_cast<const float4*>(Ws + k * 64);
#pragma unroll
        for (int j = 0; j < 16; j++) {
            float4 w = wr[j];
            acc[4 * j + 0] += xv * w.x;
            acc[4 * j + 1] += xv * w.y;
            acc[4 * j + 2] += xv * w.z;
            acc[4 * j + 3] += xv * w.w;
        }
    }

    float4* yp = reinterpret_cast<float4*>(Y + (size_t)row * 64);
#pragma unroll
    for (int i = 0; i < 16; i++) {
        float a0 = acc[4 * i + 0], a1 = acc[4 * i + 1];
        float a2 = acc[4 * i + 2], a3 = acc[4 * i + 3];
        if (ACT == 1) {
            a0 = a0 > 0.f ? a0 : expm1f(a0);
            a1 = a1 > 0.f ? a1 : expm1f(a1);
            a2 = a2 > 0.f ? a2 : expm1f(a2);
            a3 = a3 > 0.f ? a3 : expm1f(a3);
        }
        yp[i] = make_float4(a0, a1, a2, a3);
    }
}

// ---------------- Fused NGCF layer, 128 thr, dyn smem ---------------------------
// SPLIT: layer 1 reads ego from user_emb/item_emb directly
template <bool SPLIT>
__global__ void __launch_bounds__(128) layer_kernel(
    const float* __restrict__ Wg, const float* __restrict__ bg,
    const float* __restrict__ Wb, const float* __restrict__ bb,
    const float* __restrict__ eu, const float* __restrict__ ei, int kout) {
    extern __shared__ float sm[];
    float* Wgs = sm;            // 4096
    float* Wbs = sm + 4096;     // 4096
    float* ss  = sm + 8192;     // 8192 (transposed side [k][tid])
    int tid = threadIdx.x;
    for (int i = tid; i < 4096; i += 128) { Wgs[i] = Wg[i]; Wbs[i] = Wb[i]; }
    int row = blockIdx.x * 128 + tid;
    bool valid = row < NT;
    if (valid) {
        const float4* sp = reinterpret_cast<const float4*>(g_spmm + (size_t)row * 64);
#pragma unroll
        for (int i = 0; i < 16; i++) {
            float4 t = sp[i];
            ss[(4 * i + 0) * 128 + tid] = t.x;
            ss[(4 * i + 1) * 128 + tid] = t.y;
            ss[(4 * i + 2) * 128 + tid] = t.z;
            ss[(4 * i + 3) * 128 + tid] = t.w;
        }
    }
    __syncthreads();
    if (!valid) return;

    float acc[64];
#pragma unroll
    for (int j = 0; j < 64; j++) acc[j] = __ldg(bg + j) + __ldg(bb + j);

    const float* erow;
    if (SPLIT) {
        erow = (row < NU) ? (eu + (size_t)row * 64) : (ei + (size_t)(row - NU) * 64);
    } else {
        erow = g_ego + (size_t)row * 64;
    }
    for (int k = 0; k < 64; k++) {
        float s = ss[k * 128 + tid];
        float p = s * __ldg(erow + k);
        const float4* wg = reinterpret_cast<const float4*>(Wgs + k * 64);
        const float4* wb = reinterpret_cast<const float4*>(Wbs + k * 64);
#pragma unroll
        for (int j = 0; j < 16; j++) {
            float4 a = wg[j];
            float4 c = wb[j];
            acc[4 * j + 0] += s * a.x + p * c.x;
            acc[4 * j + 1] += s * a.y + p * c.y;
            acc[4 * j + 2] += s * a.z + p * c.z;
            acc[4 * j + 3] += s * a.w + p * c.w;
        }
    }

    float ssum = 0.f;
#pragma unroll
    for (int j = 0; j < 64; j++) {
        float v = acc[j];
        v = v >= 0.f ? v : 0.2f * v;
        acc[j] = v;
        ssum += v * v;
    }
    float inv = 1.f / fmaxf(sqrtf(ssum), 1e-12f);

    float4* ep = reinterpret_cast<float4*>(g_ego + (size_t)row * 64);
    float4* ap = reinterpret_cast<float4*>(g_all + (size_t)row * 256 + (size_t)kout * 64);
#pragma unroll
    for (int i = 0; i < 16; i++) {
        float4 o = make_float4(acc[4 * i + 0], acc[4 * i + 1], acc[4 * i + 2], acc[4 * i + 3]);
        ep[i] = o;
        ap[i] = make_float4(o.x * inv, o.y * inv, o.z * inv, o.w * inv);
    }
}

// ---------------- fill g_all block 0 (off critical path) ------------------------
__global__ void init_all0_kernel(const float4* __restrict__ ue, const float4* __restrict__ ie) {
    int i = blockIdx.x * blockDim.x + threadIdx.x;
    int s = gridDim.x * blockDim.x;
    const int tot = NT * 16;
    for (; i < tot; i += s) {
        int row = i >> 4;
        int c = i & 15;
        float4 v = (row < NU) ? ue[i] : ie[i - NU * 16];
        reinterpret_cast<float4*>(g_all)[(size_t)row * 64 + c] = v;
    }
}

// ---------------- final gather: out[12288, 320] ---------------------------------
__global__ void gather_kernel(const int* __restrict__ users, const int* __restrict__ pos,
                              const int* __restrict__ neg, float4* __restrict__ out) {
    int r = blockIdx.x;
    int tid = threadIdx.x;
    if (tid >= 80) return;
    const float4* allp;
    const float4* hp;
    if (r < 4096) {
        int u = __ldg(users + r);
        allp = reinterpret_cast<const float4*>(g_all + (size_t)u * 256);
        hp   = reinterpret_cast<const float4*>(g_uh + (size_t)u * 64);
    } else if (r < 8192) {
        int it = __ldg(pos + (r - 4096));
        allp = reinterpret_cast<const float4*>(g_all + ((size_t)NU + it) * 256);
        hp   = reinterpret_cast<const float4*>(g_ih + (size_t)it * 64);
    } else {
        int it = __ldg(neg + (r - 8192));
        allp = reinterpret_cast<const float4*>(g_all + ((size_t)NU + it) * 256);
        hp   = reinterpret_cast<const float4*>(g_ih + (size_t)it * 64);
    }
    float4 v;
    if (tid < 64) {
        v = allp[tid];
    } else {
        float4 h = hp[tid - 64];
        v = make_float4(fmaxf(h.x, 0.f), fmaxf(h.y, 0.f), fmaxf(h.z, 0.f), fmaxf(h.w, 0.f));
    }
    out[(size_t)r * 80 + tid] = v;
}

// ---------------- host ----------------------------------------------------------
static void build_csr(cudaStream_t st, const int* rows, const int* cols, const float* vals,
                      int nnz, int nrows, int* counts, int* off, int* rowptr,
                      int* bsums, int* ccol, float* cval) {
    zero4_kernel<<<256, 256, 0, st>>>((float4*)counts, nrows / 4);
    hist_kernel<<<2048, 256, 0, st>>>(rows, counts, nnz);
    int nb = (nrows + 1023) / 1024;
    scan_local_kernel<<<nb, 1024, 0, st>>>(counts, rowptr, bsums, nrows);
    scan_bsums_kernel<<<1, 256, 0, st>>>(bsums, nb);
    scan_add_kernel<<<nb, 1024, 0, st>>>(rowptr, off, bsums, nrows, nnz);
    scatter_kernel<<<2048, 256, 0, st>>>(rows, cols, vals, off, ccol, cval, nnz);
}

#define GEMM_SMEM  (12288 * 4)   // 48 KB
#define LAYER_SMEM (16384 * 4)   // 64 KB

extern "C" void kernel_launch(void* const* d_in, const int* in_sizes, int n_in,
                              void* d_out, int out_size) {
    const int*   users    = (const int*)d_in[0];
    const int*   pos      = (const int*)d_in[1];
    const int*   neg      = (const int*)d_in[2];
    const int*   adj_r    = (const int*)d_in[3];
    const int*   adj_c    = (const int*)d_in[4];
    const float* adj_v    = (const float*)d_in[5];
    const int*   ug_r     = (const int*)d_in[6];
    const int*   ug_c     = (const int*)d_in[7];
    const float* ug_v     = (const float*)d_in[8];
    const int*   ig_r     = (const int*)d_in[9];
    const int*   ig_c     = (const int*)d_in[10];
    const float* ig_v     = (const float*)d_in[11];
    const float* user_emb = (const float*)d_in[12];
    const float* item_emb = (const float*)d_in[13];
    const float* W_gc     = (const float*)d_in[14];
    const float* b_gc     = (const float*)d_in[15];
    const float* W_bi     = (const float*)d_in[16];
    const float* b_bi     = (const float*)d_in[17];
    const float* Wu0      = (const float*)d_in[18];
    const float* bu0      = (const float*)d_in[19];
    const float* Wu1      = (const float*)d_in[20];
    const float* bu1      = (const float*)d_in[21];
    const float* Wi0      = (const float*)d_in[22];
    const float* bi0      = (const float*)d_in[23];
    const float* Wi1      = (const float*)d_in[24];
    const float* bi1      = (const float*)d_in[25];

    const int nnz_adj = in_sizes[3];
    const int nnz_ug  = in_sizes[6];
    const int nnz_ig  = in_sizes[9];

    static cudaStream_t s1 = nullptr, s2 = nullptr;
    static cudaEvent_t evR = nullptr, ev1 = nullptr, ev2 = nullptr;
    if (s1 == nullptr) {
        cudaStreamCreateWithFlags(&s1, cudaStreamNonBlocking);
        cudaStreamCreateWithFlags(&s2, cudaStreamNonBlocking);
        cudaEventCreateWithFlags(&evR, cudaEventDisableTiming);
        cudaEventCreateWithFlags(&ev1, cudaEventDisableTiming);
        cudaEventCreateWithFlags(&ev2, cudaEventDisableTiming);
        cudaFuncSetAttribute(gemm64_kernel<0>, cudaFuncAttributeMaxDynamicSharedMemorySize, GEMM_SMEM);
        cudaFuncSetAttribute(gemm64_kernel<1>, cudaFuncAttributeMaxDynamicSharedMemorySize, GEMM_SMEM);
        cudaFuncSetAttribute(layer_kernel<true>,  cudaFuncAttributeMaxDynamicSharedMemorySize, LAYER_SMEM);
        cudaFuncSetAttribute(layer_kernel<false>, cudaFuncAttributeMaxDynamicSharedMemorySize, LAYER_SMEM);
    }

    float *spmm_p, *spmm_u, *spmm_i, *hid_u, *hid_i, *uh_p, *ih_p, *ego_p;
    cudaGetSymbolAddress((void**)&spmm_p, g_spmm);
    cudaGetSymbolAddress((void**)&spmm_u, g_spmm_u);
    cudaGetSymbolAddress((void**)&spmm_i, g_spmm_i);
    cudaGetSymbolAddress((void**)&hid_u,  g_hid_u);
    cudaGetSymbolAddress((void**)&hid_i,  g_hid_i);
    cudaGetSymbolAddress((void**)&uh_p,   g_uh);
    cudaGetSymbolAddress((void**)&ih_p,   g_ih);
    cudaGetSymbolAddress((void**)&ego_p,  g_ego);

    int *cnt_a, *cnt_u, *cnt_i, *off_a, *off_u, *off_i, *bs_a, *bs_u, *bs_i;
    int *adj_rp, *ug_rp, *ig_rp, *adj_cc, *ug_cc, *ig_cc;
    float *adj_cv, *ug_cv, *ig_cv;
    cudaGetSymbolAddress((void**)&cnt_a, g_counts_a);
    cudaGetSymbolAddress((void**)&cnt_u, g_counts_u);
    cudaGetSymbolAddress((void**)&cnt_i, g_counts_i);
    cudaGetSymbolAddress((void**)&off_a, g_off_a);
    cudaGetSymbolAddress((void**)&off_u, g_off_u);
    cudaGetSymbolAddress((void**)&off_i, g_off_i);
    cudaGetSymbolAddress((void**)&bs_a,  g_bsums_a);
    cudaGetSymbolAddress((void**)&bs_u,  g_bsums_u);
    cudaGetSymbolAddress((void**)&bs_i,  g_bsums_i);
    cudaGetSymbolAddress((void**)&adj_rp, g_adj_rp);
    cudaGetSymbolAddress((void**)&ug_rp,  g_ug_rp);
    cudaGetSymbolAddress((void**)&ig_rp,  g_ig_rp);
    cudaGetSymbolAddress((void**)&adj_cc, g_adj_col);
    cudaGetSymbolAddress((void**)&adj_cv, g_adj_val);
    cudaGetSymbolAddress((void**)&ug_cc,  g_ug_col);
    cudaGetSymbolAddress((void**)&ug_cv,  g_ug_val);
    cudaGetSymbolAddress((void**)&ig_cc,  g_ig_col);
    cudaGetSymbolAddress((void**)&ig_cv,  g_ig_val);

    // ---- fork ----
    cudaEventRecord(evR, 0);
    cudaStreamWaitEvent(s1, evR, 0);
    cudaStreamWaitEvent(s2, evR, 0);

    // ---- branch 1 (s1): g_all block0 + user MLP path ----
    init_all0_kernel<<<1024, 256, 0, s1>>>((const float4*)user_emb, (const float4*)item_emb);
    build_csr(s1, ug_r, ug_c, ug_v, nnz_ug, NU, cnt_u, off_u, ug_rp, bs_u, ug_cc, ug_cv);
    csr_spmm4_kernel<false><<<(NU + 31) / 32, 256, 0, s1>>>(ug_rp, ug_cc, ug_cv, user_emb, nullptr, spmm_u, NU);
    gemm64_kernel<1><<<(NU + 127) / 128, 128, GEMM_SMEM, s1>>>(spmm_u, Wu0, bu0, hid_u, NU);
    csr_spmm4_kernel<false><<<(NU + 31) / 32, 256, 0, s1>>>(ug_rp, ug_cc, ug_cv, hid_u, nullptr, spmm_u, NU);
    gemm64_kernel<0><<<(NU + 127) / 128, 128, GEMM_SMEM, s1>>>(spmm_u, Wu1, bu1, uh_p, NU);
    cudaEventRecord(ev1, s1);

    // ---- branch 2 (s2): item MLP path ----
    build_csr(s2, ig_r, ig_c, ig_v, nnz_ig, NI, cnt_i, off_i, ig_rp, bs_i, ig_cc, ig_cv);
    csr_spmm4_kernel<false><<<(NI + 31) / 32, 256, 0, s2>>>(ig_rp, ig_cc, ig_cv, item_emb, nullptr, spmm_i, NI);
    gemm64_kernel<1><<<(NI + 127) / 128, 128, GEMM_SMEM, s2>>>(spmm_i, Wi0, bi0, hid_i, NI);
    csr_spmm4_kernel<false><<<(NI + 31) / 32, 256, 0, s2>>>(ig_rp, ig_cc, ig_cv, hid_i, nullptr, spmm_i, NI);
    gemm64_kernel<0><<<(NI + 127) / 128, 128, GEMM_SMEM, s2>>>(spmm_i, Wi1, bi1, ih_p, NI);
    cudaEventRecord(ev2, s2);

    // ---- main stream: graph conv path (critical) ----
    build_csr(0, adj_r, adj_c, adj_v, nnz_adj, NT, cnt_a, off_a, adj_rp, bs_a, adj_cc, adj_cv);
    // layer 1: spmm + layer read embeddings directly (no init on critical path)
    csr_spmm4_kernel<true><<<(NT + 31) / 32, 256>>>(adj_rp, adj_cc, adj_cv, user_emb, item_emb, spmm_p, NT);
    layer_kernel<true><<<(NT + 127) / 128, 128, LAYER_SMEM>>>(
        W_gc, b_gc, W_bi, b_bi, user_emb, item_emb, 1);
    for (int k = 1; k < 3; k++) {
        csr_spmm4_kernel<false><<<(NT + 31) / 32, 256>>>(adj_rp, adj_cc, adj_cv, ego_p, nullptr, spmm_p, NT);
        layer_kernel<false><<<(NT + 127) / 128, 128, LAYER_SMEM>>>(
            W_gc + (size_t)k * 4096, b_gc + (size_t)k * 64,
            W_bi + (size_t)k * 4096, b_bi + (size_t)k * 64, nullptr, nullptr, k + 1);
    }

    // ---- join + final gather ----
    cudaStreamWaitEvent(0, ev1, 0);
    cudaStreamWaitEvent(0, ev2, 0);
    gather_kernel<<<12288, 96>>>(users, pos, neg, (float4*)d_out);
}

// round 12
// speedup vs baseline: 1.7875x; 1.1235x over previous
#include <cuda_runtime.h>
#include <cuda_fp16.h>
#include <math.h>

#define NU 60000
#define NI 120000
#define NT 180000   // NU + NI
#define NNZ_ADJ 3600000
#define NNZ_UG  960000
#define NNZ_IG  1920000

typedef unsigned long long ull;

// ---------------- device scratch ------------------------------------------------
__device__ float  g_spmm  [(size_t)NT * 64];
__device__ float  g_spmm_u[(size_t)NU * 64];
__device__ float  g_spmm_i[(size_t)NI * 64];
__device__ float  g_uh    [(size_t)NU * 64];
__device__ float  g_ih    [(size_t)NI * 64];
__device__ float  g_ego   [(size_t)NT * 64];   // fp32 ego (bi-term input)
__device__ float  g_all   [(size_t)NT * 256];
__device__ __half g_emb_h [(size_t)NT * 64];   // half embeddings [user ; item]
__device__ __half g_ego_h [(size_t)NT * 64];   // half ego (spmm input, layers 2-3)
__device__ __half g_hid_uh[(size_t)NU * 64];   // half user MLP hidden
__device__ __half g_hid_ih[(size_t)NI * 64];   // half item MLP hidden

// CSR storage
__device__ int   g_adj_col[NNZ_ADJ];
__device__ float g_adj_val[NNZ_ADJ];
__device__ int   g_adj_rp [NT + 1];
__device__ int   g_ug_col [NNZ_UG];
__device__ float g_ug_val [NNZ_UG];
__device__ int   g_ug_rp  [NU + 1];
__device__ int   g_ig_col [NNZ_IG];
__device__ float g_ig_val [NNZ_IG];
__device__ int   g_ig_rp  [NI + 1];
__device__ int   g_counts_a[NT];
__device__ int   g_counts_u[NU];
__device__ int   g_counts_i[NI];
__device__ int   g_off_a   [NT];
__device__ int   g_off_u   [NU];
__device__ int   g_off_i   [NI];
__device__ int   g_bsums_a [256];
__device__ int   g_bsums_u [256];
__device__ int   g_bsums_i [256];

// ---------------- f32x2 helpers -------------------------------------------------
__device__ __forceinline__ ull pk2(float x, float y) {
    ull r; asm("mov.b64 %0, {%1, %2};" : "=l"(r) : "f"(x), "f"(y)); return r;
}
__device__ __forceinline__ void upk2(ull v, float& x, float& y) {
    asm("mov.b64 {%0, %1}, %2;" : "=f"(x), "=f"(y) : "l"(v));
}
__device__ __forceinline__ void fma2(ull& d, ull a, ull b) {
    asm("fma.rn.f32x2 %0, %1, %2, %0;" : "+l"(d) : "l"(a), "l"(b));
}
__device__ __forceinline__ unsigned h2u(float a, float b) {
    __half2 h = __floats2half2_rn(a, b);
    return *reinterpret_cast<unsigned*>(&h);
}

// ---------------- zero ----------------------------------------------------------
__global__ void zero4_kernel(float4* __restrict__ p, int n4) {
    int i = blockIdx.x * blockDim.x + threadIdx.x;
    int s = gridDim.x * blockDim.x;
    float4 z = make_float4(0.f, 0.f, 0.f, 0.f);
    for (; i < n4; i += s) p[i] = z;
}

// ---------------- CSR build: histogram ------------------------------------------
__global__ void hist_kernel(const int* __restrict__ rows, int* __restrict__ counts, int nnz) {
    int i = blockIdx.x * blockDim.x + threadIdx.x;
    int s = gridDim.x * blockDim.x;
    for (; i < nnz; i += s) atomicAdd(counts + __ldg(rows + i), 1);
}

// ---------------- two-level scan -------------------------------------------------
__global__ void __launch_bounds__(1024) scan_local_kernel(
    const int* __restrict__ counts, int* __restrict__ rowptr,
    int* __restrict__ bsums, int n) {
    __shared__ int ws[32];
    int tid = threadIdx.x, lane = tid & 31, w = tid >> 5;
    int i = blockIdx.x * 1024 + tid;
    int v = (i < n) ? counts[i] : 0;
    int x = v;
#pragma unroll
    for (int d = 1; d < 32; d <<= 1) {
        int y = __shfl_up_sync(0xffffffffu, x, d);
        if (lane >= d) x += y;
    }
    if (lane == 31) ws[w] = x;
    __syncthreads();
    if (w == 0) {
        int s = ws[lane];
#pragma unroll
        for (int d = 1; d < 32; d <<= 1) {
            int y = __shfl_up_sync(0xffffffffu, s, d);
            if (lane >= d) s += y;
        }
        ws[lane] = s;
    }
    __syncthreads();
    int excl = x - v + (w > 0 ? ws[w - 1] : 0);
    if (i < n) rowptr[i] = excl;
    if (tid == 1023) bsums[blockIdx.x] = excl + v;
}

__global__ void __launch_bounds__(256) scan_bsums_kernel(int* __restrict__ bsums, int nb) {
    __shared__ int ws[8];
    int tid = threadIdx.x, lane = tid & 31, w = tid >> 5;
    int v = (tid < nb) ? bsums[tid] : 0;
    int x = v;
#pragma unroll
    for (int d = 1; d < 32; d <<= 1) {
        int y = __shfl_up_sync(0xffffffffu, x, d);
        if (lane >= d) x += y;
    }
    if (lane == 31) ws[w] = x;
    __syncthreads();
    if (w == 0) {
        int s = (lane < 8) ? ws[lane] : 0;
#pragma unroll
        for (int d = 1; d < 8; d <<= 1) {
            int y = __shfl_up_sync(0xffffffffu, s, d);
            if (lane >= d) s += y;
        }
        if (lane < 8) ws[lane] = s;
    }
    __syncthreads();
    int excl = x - v + (w > 0 ? ws[w - 1] : 0);
    __syncthreads();
    if (tid < nb) bsums[tid] = excl;
}

__global__ void scan_add_kernel(int* __restrict__ rowptr, int* __restrict__ off,
                                const int* __restrict__ bsums, int n, int nnz) {
    int i = blockIdx.x * blockDim.x + threadIdx.x;
    if (i < n) {
        int v = rowptr[i] + __ldg(bsums + (i >> 10));
        rowptr[i] = v;
        off[i] = v;
    }
    if (i == 0) rowptr[n] = nnz;
}

// ---------------- CSR build: scatter --------------------------------------------
__global__ void scatter_kernel(const int* __restrict__ rows, const int* __restrict__ cols,
                               const float* __restrict__ vals, int* __restrict__ off,
                               int* __restrict__ ccol, float* __restrict__ cval, int nnz) {
    int i = blockIdx.x * blockDim.x + threadIdx.x;
    int s = gridDim.x * blockDim.x;
    for (; i < nnz; i += s) {
        int r = __ldg(rows + i);
        int p = atomicAdd(off + r, 1);
        ccol[p] = __ldg(cols + i);
        cval[p] = __ldg(vals + i);
    }
}

// ---------------- convert fp32 embeddings -> half (off critical path) ----------
__global__ void to_half_kernel(const float4* __restrict__ ue, const float4* __restrict__ ie,
                               uint2* __restrict__ dst) {
    int i = blockIdx.x * blockDim.x + threadIdx.x;
    int s = gridDim.x * blockDim.x;
    const int tot = NT * 16;
    for (; i < tot; i += s) {
        int row = i >> 4;
        float4 v = (row < NU) ? ue[i] : ie[i - NU * 16];
        uint2 u;
        u.x = h2u(v.x, v.y);
        u.y = h2u(v.z, v.w);
        dst[i] = u;
    }
}

// ---------------- CSR SpMM: 4 rows/warp, 8 lanes/row, half operand --------------
__global__ void __launch_bounds__(256) csr_spmm4_kernel(
    const int* __restrict__ rowptr, const int* __restrict__ cols,
    const float* __restrict__ vals, const __half* __restrict__ x,
    float* __restrict__ out, int nrows) {
    int warp = (blockIdx.x * blockDim.x + threadIdx.x) >> 5;
    int lane = threadIdx.x & 31;
    int g    = lane >> 3;         // row group 0..3
    int sub  = lane & 7;          // 8 floats each
    int row  = warp * 4 + g;
    bool valid = row < nrows;
    int start = valid ? __ldg(rowptr + row)     : 0;
    int end   = valid ? __ldg(rowptr + row + 1) : 0;

    float4 a0 = make_float4(0.f, 0.f, 0.f, 0.f);
    float4 a1 = make_float4(0.f, 0.f, 0.f, 0.f);

    for (int j = start; j < end; j++) {
        int   c = __ldg(cols + j);   // 8-way broadcast within group
        float v = __ldg(vals + j);
        // one 16B load = 8 halves, the lane's whole slice
        uint4 xv = __ldg(reinterpret_cast<const uint4*>(x + (size_t)c * 64 + sub * 8));
        float2 f0 = __half22float2(*reinterpret_cast<__half2*>(&xv.x));
        float2 f1 = __half22float2(*reinterpret_cast<__half2*>(&xv.y));
        float2 f2 = __half22float2(*reinterpret_cast<__half2*>(&xv.z));
        float2 f3 = __half22float2(*reinterpret_cast<__half2*>(&xv.w));
        a0.x = fmaf(v, f0.x, a0.x); a0.y = fmaf(v, f0.y, a0.y);
        a0.z = fmaf(v, f1.x, a0.z); a0.w = fmaf(v, f1.y, a0.w);
        a1.x = fmaf(v, f2.x, a1.x); a1.y = fmaf(v, f2.y, a1.y);
        a1.z = fmaf(v, f3.x, a1.z); a1.w = fmaf(v, f3.y, a1.w);
    }
    if (valid) {
        float4* op = reinterpret_cast<float4*>(out + (size_t)row * 64 + sub * 8);
        op[0] = a0;
        op[1] = a1;
    }
}

// ---------------- GEMM: Y = act(X[R,64] @ W[64,64] + b), FFMA2 ------------------
// HOUT: write half output (Yh) instead of fp32 (Y)
template <int ACT, bool HOUT>
__global__ void __launch_bounds__(128) gemm64_kernel(
    const float* __restrict__ X, const float* __restrict__ W,
    const float* __restrict__ b, float* __restrict__ Y,
    __half* __restrict__ Yh, int R) {
    extern __shared__ float sm[];
    float* Ws = sm;           // 4096
    float* xs = sm + 4096;    // 8192 (transposed [k][tid])
    int tid = threadIdx.x;
    for (int i = tid; i < 4096; i += 128) Ws[i] = W[i];
    int row = blockIdx.x * 128 + tid;
    bool valid = row < R;
    if (valid) {
        const float4* xp = reinterpret_cast<const float4*>(X + (size_t)row * 64);
#pragma unroll
        for (int i = 0; i < 16; i++) {
            float4 t = xp[i];
            xs[(4 * i + 0) * 128 + tid] = t.x;
            xs[(4 * i + 1) * 128 + tid] = t.y;
            xs[(4 * i + 2) * 128 + tid] = t.z;
            xs[(4 * i + 3) * 128 + tid] = t.w;
        }
    }
    __syncthreads();
    if (!valid) return;

    ull acc2[32];
#pragma unroll
    for (int j = 0; j < 32; j++) acc2[j] = pk2(__ldg(b + 2 * j), __ldg(b + 2 * j + 1));

    for (int k = 0; k < 64; k++) {
        float xv = xs[k * 128 + tid];
        ull xv2 = pk2(xv, xv);
        const ulonglong2* wr = reinterpret_cast<const ulonglong2*>(Ws + k * 64);
#pragma unroll
        for (int j = 0; j < 16; j++) {
            ulonglong2 w = wr[j];
            fma2(acc2[2 * j + 0], xv2, w.x);
            fma2(acc2[2 * j + 1], xv2, w.y);
        }
    }

    float acc[64];
#pragma unroll
    for (int j = 0; j < 32; j++) upk2(acc2[j], acc[2 * j], acc[2 * j + 1]);
#pragma unroll
    for (int j = 0; j < 64; j++) {
        float a = acc[j];
        if (ACT == 1) a = a > 0.f ? a : expm1f(a);
        acc[j] = a;
    }

    if (HOUT) {
        uint4* yp = reinterpret_cast<uint4*>(Yh + (size_t)row * 64);
#pragma unroll
        for (int i = 0; i < 8; i++) {
            uint4 u;
            u.x = h2u(acc[8 * i + 0], acc[8 * i + 1]);
            u.y = h2u(acc[8 * i + 2], acc[8 * i + 3]);
            u.z = h2u(acc[8 * i + 4], acc[8 * i + 5]);
            u.w = h2u(acc[8 * i + 6], acc[8 * i + 7]);
            yp[i] = u;
        }
    } else {
        float4* yp = reinterpret_cast<float4*>(Y + (size_t)row * 64);
#pragma unroll
        for (int i = 0; i < 16; i++)
            yp[i] = make_float4(acc[4 * i + 0], acc[4 * i + 1], acc[4 * i + 2], acc[4 * i + 3]);
    }
}

// ---------------- Fused NGCF layer, FFMA2 ---------------------------------------
template <bool SPLIT>
__global__ void __launch_bounds__(128) layer_kernel(
    const float* __restrict__ Wg, const float* __restrict__ bg,
    const float* __restrict__ Wb, const float* __restrict__ bb,
    const float* __restrict__ eu, const float* __restrict__ ei, int kout) {
    extern __shared__ float sm[];
    float* Wgs = sm;            // 4096
    float* Wbs = sm + 4096;     // 4096
    float* ss  = sm + 8192;     // 8192 (transposed side [k][tid])
    int tid = threadIdx.x;
    for (int i = tid; i < 4096; i += 128) { Wgs[i] = Wg[i]; Wbs[i] = Wb[i]; }
    int row = blockIdx.x * 128 + tid;
    bool valid = row < NT;
    if (valid) {
        const float4* sp = reinterpret_cast<const float4*>(g_spmm + (size_t)row * 64);
#pragma unroll
        for (int i = 0; i < 16; i++) {
            float4 t = sp[i];
            ss[(4 * i + 0) * 128 + tid] = t.x;
            ss[(4 * i + 1) * 128 + tid] = t.y;
            ss[(4 * i + 2) * 128 + tid] = t.z;
            ss[(4 * i + 3) * 128 + tid] = t.w;
        }
    }
    __syncthreads();
    if (!valid) return;

    ull acc2[32];
#pragma unroll
    for (int j = 0; j < 32; j++)
        acc2[j] = pk2(__ldg(bg + 2 * j) + __ldg(bb + 2 * j),
                      __ldg(bg + 2 * j + 1) + __ldg(bb + 2 * j + 1));

    const float* erow;
    if (SPLIT) {
        erow = (row < NU) ? (eu + (size_t)row * 64) : (ei + (size_t)(row - NU) * 64);
    } else {
        erow = g_ego + (size_t)row * 64;
    }
    for (int k = 0; k < 64; k++) {
        float s = ss[k * 128 + tid];
        float p = s * __ldg(erow + k);
        ull s2 = pk2(s, s);
        ull p2 = pk2(p, p);
        const ulonglong2* wg = reinterpret_cast<const ulonglong2*>(Wgs + k * 64);
        const ulonglong2* wb = reinterpret_cast<const ulonglong2*>(Wbs + k * 64);
#pragma unroll
        for (int j = 0; j < 16; j++) {
            ulonglong2 a = wg[j];
            ulonglong2 c = wb[j];
            fma2(acc2[2 * j + 0], s2, a.x);
            fma2(acc2[2 * j + 1], s2, a.y);
            fma2(acc2[2 * j + 0], p2, c.x);
            fma2(acc2[2 * j + 1], p2, c.y);
        }
    }

    float acc[64];
#pragma unroll
    for (int j = 0; j < 32; j++) upk2(acc2[j], acc[2 * j], acc[2 * j + 1]);

    float ssum = 0.f;
#pragma unroll
    for (int j = 0; j < 64; j++) {
        float v = acc[j];
        v = v >= 0.f ? v : 0.2f * v;
        acc[j] = v;
        ssum += v * v;
    }
    float inv = 1.f / fmaxf(sqrtf(ssum), 1e-12f);

    float4* ep = reinterpret_cast<float4*>(g_ego + (size_t)row * 64);
    float4* ap = reinterpret_cast<float4*>(g_all + (size_t)row * 256 + (size_t)kout * 64);
#pragma unroll
    for (int i = 0; i < 16; i++) {
        float4 o = make_float4(acc[4 * i + 0], acc[4 * i + 1], acc[4 * i + 2], acc[4 * i + 3]);
        ep[i] = o;
        ap[i] = make_float4(o.x * inv, o.y * inv, o.z * inv, o.w * inv);
    }
    // half ego for next layer's spmm
    uint4* hp = reinterpret_cast<uint4*>(g_ego_h + (size_t)row * 64);
#pragma unroll
    for (int i = 0; i < 8; i++) {
        uint4 u;
        u.x = h2u(acc[8 * i + 0], acc[8 * i + 1]);
        u.y = h2u(acc[8 * i + 2], acc[8 * i + 3]);
        u.z = h2u(acc[8 * i + 4], acc[8 * i + 5]);
        u.w = h2u(acc[8 * i + 6], acc[8 * i + 7]);
        hp[i] = u;
    }
}

// ---------------- fill g_all block 0 (off critical path) ------------------------
__global__ void init_all0_kernel(const float4* __restrict__ ue, const float4* __restrict__ ie) {
    int i = blockIdx.x * blockDim.x + threadIdx.x;
    int s = gridDim.x * blockDim.x;
    const int tot = NT * 16;
    for (; i < tot; i += s) {
        int row = i >> 4;
        int c = i & 15;
        float4 v = (row < NU) ? ue[i] : ie[i - NU * 16];
        reinterpret_cast<float4*>(g_all)[(size_t)row * 64 + c] = v;
    }
}

// ---------------- final gather: out[12288, 320] ---------------------------------
__global__ void gather_kernel(const int* __restrict__ users, const int* __restrict__ pos,
                              const int* __restrict__ neg, float4* __restrict__ out) {
    int r = blockIdx.x;
    int tid = threadIdx.x;
    if (tid >= 80) return;
    const float4* allp;
    const float4* hp;
    if (r < 4096) {
        int u = __ldg(users + r);
        allp = reinterpret_cast<const float4*>(g_all + (size_t)u * 256);
        hp   = reinterpret_cast<const float4*>(g_uh + (size_t)u * 64);
    } else if (r < 8192) {
        int it = __ldg(pos + (r - 4096));
        allp = reinterpret_cast<const float4*>(g_all + ((size_t)NU + it) * 256);
        hp   = reinterpret_cast<const float4*>(g_ih + (size_t)it * 64);
    } else {
        int it = __ldg(neg + (r - 8192));
        allp = reinterpret_cast<const float4*>(g_all + ((size_t)NU + it) * 256);
        hp   = reinterpret_cast<const float4*>(g_ih + (size_t)it * 64);
    }
    float4 v;
    if (tid < 64) {
        v = allp[tid];
    } else {
        float4 h = hp[tid - 64];
        v = make_float4(fmaxf(h.x, 0.f), fmaxf(h.y, 0.f), fmaxf(h.z, 0.f), fmaxf(h.w, 0.f));
    }
    out[(size_t)r * 80 + tid] = v;
}

// ---------------- host ----------------------------------------------------------
static void build_csr(cudaStream_t st, const int* rows, const int* cols, const float* vals,
                      int nnz, int nrows, int* counts, int* off, int* rowptr,
                      int* bsums, int* ccol, float* cval) {
    zero4_kernel<<<256, 256, 0, st>>>((float4*)counts, nrows / 4);
    hist_kernel<<<2048, 256, 0, st>>>(rows, counts, nnz);
    int nb = (nrows + 1023) / 1024;
    scan_local_kernel<<<nb, 1024, 0, st>>>(counts, rowptr, bsums, nrows);
    scan_bsums_kernel<<<1, 256, 0, st>>>(bsums, nb);
    scan_add_kernel<<<nb, 1024, 0, st>>>(rowptr, off, bsums, nrows, nnz);
    scatter_kernel<<<2048, 256, 0, st>>>(rows, cols, vals, off, ccol, cval, nnz);
}

#define GEMM_SMEM  (12288 * 4)   // 48 KB
#define LAYER_SMEM (16384 * 4)   // 64 KB

extern "C" void kernel_launch(void* const* d_in, const int* in_sizes, int n_in,
                              void* d_out, int out_size) {
    const int*   users    = (const int*)d_in[0];
    const int*   pos      = (const int*)d_in[1];
    const int*   neg      = (const int*)d_in[2];
    const int*   adj_r    = (const int*)d_in[3];
    const int*   adj_c    = (const int*)d_in[4];
    const float* adj_v    = (const float*)d_in[5];
    const int*   ug_r     = (const int*)d_in[6];
    const int*   ug_c     = (const int*)d_in[7];
    const float* ug_v     = (const float*)d_in[8];
    const int*   ig_r     = (const int*)d_in[9];
    const int*   ig_c     = (const int*)d_in[10];
    const float* ig_v     = (const float*)d_in[11];
    const float* user_emb = (const float*)d_in[12];
    const float* item_emb = (const float*)d_in[13];
    const float* W_gc     = (const float*)d_in[14];
    const float* b_gc     = (const float*)d_in[15];
    const float* W_bi     = (const float*)d_in[16];
    const float* b_bi     = (const float*)d_in[17];
    const float* Wu0      = (const float*)d_in[18];
    const float* bu0      = (const float*)d_in[19];
    const float* Wu1      = (const float*)d_in[20];
    const float* bu1      = (const float*)d_in[21];
    const float* Wi0      = (const float*)d_in[22];
    const float* bi0      = (const float*)d_in[23];
    const float* Wi1      = (const float*)d_in[24];
    const float* bi1      = (const float*)d_in[25];

    const int nnz_adj = in_sizes[3];
    const int nnz_ug  = in_sizes[6];
    const int nnz_ig  = in_sizes[9];

    static cudaStream_t s1 = nullptr, s2 = nullptr, s3 = nullptr;
    static cudaEvent_t evR = nullptr, ev1 = nullptr, ev2 = nullptr, ev3 = nullptr;
    if (s1 == nullptr) {
        cudaStreamCreateWithFlags(&s1, cudaStreamNonBlocking);
        cudaStreamCreateWithFlags(&s2, cudaStreamNonBlocking);
        cudaStreamCreateWithFlags(&s3, cudaStreamNonBlocking);
        cudaEventCreateWithFlags(&evR, cudaEventDisableTiming);
        cudaEventCreateWithFlags(&ev1, cudaEventDisableTiming);
        cudaEventCreateWithFlags(&ev2, cudaEventDisableTiming);
        cudaEventCreateWithFlags(&ev3, cudaEventDisableTiming);
        cudaFuncSetAttribute(gemm64_kernel<0, false>, cudaFuncAttributeMaxDynamicSharedMemorySize, GEMM_SMEM);
        cudaFuncSetAttribute(gemm64_kernel<1, true>,  cudaFuncAttributeMaxDynamicSharedMemorySize, GEMM_SMEM);
        cudaFuncSetAttribute(layer_kernel<true>,  cudaFuncAttributeMaxDynamicSharedMemorySize, LAYER_SMEM);
        cudaFuncSetAttribute(layer_kernel<false>, cudaFuncAttributeMaxDynamicSharedMemorySize, LAYER_SMEM);
    }

    float *spmm_p, *spmm_u, *spmm_i, *uh_p, *ih_p;
    __half *emb_h, *ego_h, *hid_uh, *hid_ih;
    cudaGetSymbolAddress((void**)&spmm_p, g_spmm);
    cudaGetSymbolAddress((void**)&spmm_u, g_spmm_u);
    cudaGetSymbolAddress((void**)&spmm_i, g_spmm_i);
    cudaGetSymbolAddress((void**)&uh_p,   g_uh);
    cudaGetSymbolAddress((void**)&ih_p,   g_ih);
    cudaGetSymbolAddress((void**)&emb_h,  g_emb_h);
    cudaGetSymbolAddress((void**)&ego_h,  g_ego_h);
    cudaGetSymbolAddress((void**)&hid_uh, g_hid_uh);
    cudaGetSymbolAddress((void**)&hid_ih, g_hid_ih);

    int *cnt_a, *cnt_u, *cnt_i, *off_a, *off_u, *off_i, *bs_a, *bs_u, *bs_i;
    int *adj_rp, *ug_rp, *ig_rp, *adj_cc, *ug_cc, *ig_cc;
    float *adj_cv, *ug_cv, *ig_cv;
    cudaGetSymbolAddress((void**)&cnt_a, g_counts_a);
    cudaGetSymbolAddress((void**)&cnt_u, g_counts_u);
    cudaGetSymbolAddress((void**)&cnt_i, g_counts_i);
    cudaGetSymbolAddress((void**)&off_a, g_off_a);
    cudaGetSymbolAddress((void**)&off_u, g_off_u);
    cudaGetSymbolAddress((void**)&off_i, g_off_i);
    cudaGetSymbolAddress((void**)&bs_a,  g_bsums_a);
    cudaGetSymbolAddress((void**)&bs_u,  g_bsums_u);
    cudaGetSymbolAddress((void**)&bs_i,  g_bsums_i);
    cudaGetSymbolAddress((void**)&adj_rp, g_adj_rp);
    cudaGetSymbolAddress((void**)&ug_rp,  g_ug_rp);
    cudaGetSymbolAddress((void**)&ig_rp,  g_ig_rp);
    cudaGetSymbolAddress((void**)&adj_cc, g_adj_col);
    cudaGetSymbolAddress((void**)&adj_cv, g_adj_val);
    cudaGetSymbolAddress((void**)&ug_cc,  g_ug_col);
    cudaGetSymbolAddress((void**)&ug_cv,  g_ug_val);
    cudaGetSymbolAddress((void**)&ig_cc,  g_ig_col);
    cudaGetSymbolAddress((void**)&ig_cv,  g_ig_val);

    // ---- fork ----
    cudaEventRecord(evR, 0);
    cudaStreamWaitEvent(s1, evR, 0);
    cudaStreamWaitEvent(s2, evR, 0);
    cudaStreamWaitEvent(s3, evR, 0);

    // ---- s3: fp32 -> half embedding conversion ----
    to_half_kernel<<<1024, 256, 0, s3>>>((const float4*)user_emb, (const float4*)item_emb,
                                         (uint2*)emb_h);
    cudaEventRecord(ev3, s3);

    // ---- branch 1 (s1): g_all block0 + user MLP path ----
    init_all0_kernel<<<1024, 256, 0, s1>>>((const float4*)user_emb, (const float4*)item_emb);
    build_csr(s1, ug_r, ug_c, ug_v, nnz_ug, NU, cnt_u, off_u, ug_rp, bs_u, ug_cc, ug_cv);
    cudaStreamWaitEvent(s1, ev3, 0);
    csr_spmm4_kernel<<<(NU + 31) / 32, 256, 0, s1>>>(ug_rp, ug_cc, ug_cv, emb_h, spmm_u, NU);
    gemm64_kernel<1, true><<<(NU + 127) / 128, 128, GEMM_SMEM, s1>>>(spmm_u, Wu0, bu0, nullptr, hid_uh, NU);
    csr_spmm4_kernel<<<(NU + 31) / 32, 256, 0, s1>>>(ug_rp, ug_cc, ug_cv, hid_uh, spmm_u, NU);
    gemm64_kernel<0, false><<<(NU + 127) / 128, 128, GEMM_SMEM, s1>>>(spmm_u, Wu1, bu1, uh_p, nullptr, NU);
    cudaEventRecord(ev1, s1);

    // ---- branch 2 (s2): item MLP path ----
    build_csr(s2, ig_r, ig_c, ig_v, nnz_ig, NI, cnt_i, off_i, ig_rp, bs_i, ig_cc, ig_cv);
    cudaStreamWaitEvent(s2, ev3, 0);
    csr_spmm4_kernel<<<(NI + 31) / 32, 256, 0, s2>>>(ig_rp, ig_cc, ig_cv, emb_h + (size_t)NU * 64, spmm_i, NI);
    gemm64_kernel<1, true><<<(NI + 127) / 128, 128, GEMM_SMEM, s2>>>(spmm_i, Wi0, bi0, nullptr, hid_ih, NI);
    csr_spmm4_kernel<<<(NI + 31) / 32, 256, 0, s2>>>(ig_rp, ig_cc, ig_cv, hid_ih, spmm_i, NI);
    gemm64_kernel<0, false><<<(NI + 127) / 128, 128, GEMM_SMEM, s2>>>(spmm_i, Wi1, bi1, ih_p, nullptr, NI);
    cudaEventRecord(ev2, s2);

    // ---- main stream: graph conv path (critical) ----
    build_csr(0, adj_r, adj_c, adj_v, nnz_adj, NT, cnt_a, off_a, adj_rp, bs_a, adj_cc, adj_cv);
    cudaStreamWaitEvent(0, ev3, 0);
    csr_spmm4_kernel<<<(NT + 31) / 32, 256>>>(adj_rp, adj_cc, adj_cv, emb_h, spmm_p, NT);
    layer_kernel<true><<<(NT + 127) / 128, 128, LAYER_SMEM>>>(
        W_gc, b_gc, W_bi, b_bi, user_emb, item_emb, 1);
    for (int k = 1; k < 3; k++) {
        csr_spmm4_kernel<<<(NT + 31) / 32, 256>>>(adj_rp, adj_cc, adj_cv, ego_h, spmm_p, NT);
        layer_kernel<false><<<(NT + 127) / 128, 128, LAYER_SMEM>>>(
            W_gc + (size_t)k * 4096, b_gc + (size_t)k * 64,
            W_bi + (size_t)k * 4096, b_bi + (size_t)k * 64, nullptr, nullptr, k + 1);
    }

    // ---- join + final gather ----
    cudaStreamWaitEvent(0, ev1, 0);
    cudaStreamWaitEvent(0, ev2, 0);
    gather_kernel<<<12288, 96>>>(users, pos, neg, (float4*)d_out);
}

// round 13
// speedup vs baseline: 1.8456x; 1.0325x over previous
#include <cuda_runtime.h>
#include <cuda_fp16.h>
#include <math.h>

#define NU 60000
#define NI 120000
#define NT 180000   // NU + NI
#define NNZ_ADJ 3600000
#define NNZ_UG  960000
#define NNZ_IG  1920000

typedef unsigned long long ull;

// ---------------- device scratch ------------------------------------------------
__device__ float  g_spmm  [(size_t)NT * 64];
__device__ float  g_spmm_u[(size_t)NU * 64];
__device__ float  g_spmm_i[(size_t)NI * 64];
__device__ float  g_uh    [(size_t)NU * 64];
__device__ float  g_ih    [(size_t)NI * 64];
__device__ float  g_ego   [(size_t)NT * 64];   // fp32 ego (bi-term input)
__device__ float  g_all   [(size_t)NT * 256];
__device__ __half g_emb_h [(size_t)NT * 64];   // half embeddings [user ; item]
__device__ __half g_ego_h [(size_t)NT * 64];   // half ego (spmm input, layers 2-3)
__device__ __half g_hid_uh[(size_t)NU * 64];   // half user MLP hidden
__device__ __half g_hid_ih[(size_t)NI * 64];   // half item MLP hidden

// CSR storage: fused (col, val-bits) pairs
__device__ int2  g_adj_cv[NNZ_ADJ];
__device__ int   g_adj_rp[NT + 1];
__device__ int2  g_ug_cv [NNZ_UG];
__device__ int   g_ug_rp [NU + 1];
__device__ int2  g_ig_cv [NNZ_IG];
__device__ int   g_ig_rp [NI + 1];
// per-branch build scratch
__device__ int   g_counts_a[NT];
__device__ int   g_counts_u[NU];
__device__ int   g_counts_i[NI];
__device__ int   g_off_a   [NT];
__device__ int   g_off_u   [NU];
__device__ int   g_off_i   [NI];
__device__ ull   g_stat_a  [192];
__device__ ull   g_stat_u  [192];
__device__ ull   g_stat_i  [192];
__device__ int   g_tkt_a, g_tkt_u, g_tkt_i;

// ---------------- f32x2 helpers -------------------------------------------------
__device__ __forceinline__ ull pk2(float x, float y) {
    ull r; asm("mov.b64 %0, {%1, %2};" : "=l"(r) : "f"(x), "f"(y)); return r;
}
__device__ __forceinline__ void upk2(ull v, float& x, float& y) {
    asm("mov.b64 {%0, %1}, %2;" : "=f"(x), "=f"(y) : "l"(v));
}
__device__ __forceinline__ void fma2(ull& d, ull a, ull b) {
    asm("fma.rn.f32x2 %0, %1, %2, %0;" : "+l"(d) : "l"(a), "l"(b));
}
__device__ __forceinline__ unsigned h2u(float a, float b) {
    __half2 h = __floats2half2_rn(a, b);
    return *reinterpret_cast<unsigned*>(&h);
}

// ---------------- build reset: counts + lookback status + ticket ----------------
__global__ void reset_kernel(int4* __restrict__ counts, int n4,
                             ull* __restrict__ status, int* __restrict__ ticket) {
    int i = blockIdx.x * blockDim.x + threadIdx.x;
    int s = gridDim.x * blockDim.x;
    int4 z = make_int4(0, 0, 0, 0);
    for (int k = i; k < n4; k += s) counts[k] = z;
    if (i < 192) status[i] = 0ull;
    if (i == 0) *ticket = 0;
}

// ---------------- CSR build: histogram ------------------------------------------
__global__ void hist_kernel(const int* __restrict__ rows, int* __restrict__ counts, int nnz) {
    int i = blockIdx.x * blockDim.x + threadIdx.x;
    int s = gridDim.x * blockDim.x;
    for (; i < nnz; i += s) atomicAdd(counts + __ldg(rows + i), 1);
}

// ---------------- single-kernel decoupled-lookback exclusive scan ----------------
// status word: flag in bits[62:64) (1=aggregate, 2=prefix), value in low 32 bits
__global__ void __launch_bounds__(1024) scan_lookback_kernel(
    const int* __restrict__ counts, int* __restrict__ rowptr, int* __restrict__ off,
    ull* __restrict__ status, int* __restrict__ ticket, int n, int nnz) {
    __shared__ int ws[32];
    __shared__ int tile_s;
    __shared__ int exc_s;
    int tid = threadIdx.x, lane = tid & 31, w = tid >> 5;
    if (tid == 0) tile_s = atomicAdd(ticket, 1);
    __syncthreads();
    int tile = tile_s;

    int i = tile * 1024 + tid;
    int v = (i < n) ? counts[i] : 0;
    int x = v;
#pragma unroll
    for (int d = 1; d < 32; d <<= 1) {
        int y = __shfl_up_sync(0xffffffffu, x, d);
        if (lane >= d) x += y;
    }
    if (lane == 31) ws[w] = x;
    __syncthreads();
    if (w == 0) {
        int s = ws[lane];
#pragma unroll
        for (int d = 1; d < 32; d <<= 1) {
            int y = __shfl_up_sync(0xffffffffu, s, d);
            if (lane >= d) s += y;
        }
        ws[lane] = s;
    }
    __syncthreads();
    int T = ws[31];                               // block total
    int local_excl = x - v + (w > 0 ? ws[w - 1] : 0);

    if (tid == 0) {
        if (tile == 0) {
            atomicExch(status + 0, ((ull)2 << 62) | (unsigned)T);
            exc_s = 0;
        } else {
            atomicExch(status + tile, ((ull)1 << 62) | (unsigned)T);
            int excl = 0;
            int p = tile - 1;
            while (true) {
                ull s;
                do { s = atomicAdd(status + p, 0ull); } while ((s >> 62) == 0);
                excl += (int)(s & 0xFFFFFFFFull);
                if ((s >> 62) == 2ull) break;
                p--;
            }
            exc_s = excl;
            atomicExch(status + tile, ((ull)2 << 62) | (unsigned)(excl + T));
        }
    }
    __syncthreads();
    int base = exc_s;
    if (i < n) {
        int e = base + local_excl;
        rowptr[i] = e;
        off[i]    = e;
    }
    if (tile == 0 && tid == 0) rowptr[n] = nnz;
}

// ---------------- CSR build: scatter (fused col+val) ----------------------------
__global__ void scatter_kernel(const int* __restrict__ rows, const int* __restrict__ cols,
                               const float* __restrict__ vals, int* __restrict__ off,
                               int2* __restrict__ cv, int nnz) {
    int i = blockIdx.x * blockDim.x + threadIdx.x;
    int s = gridDim.x * blockDim.x;
    for (; i < nnz; i += s) {
        int r = __ldg(rows + i);
        int p = atomicAdd(off + r, 1);
        cv[p] = make_int2(__ldg(cols + i), __float_as_int(__ldg(vals + i)));
    }
}

// ---------------- convert fp32 embeddings -> half -------------------------------
__global__ void to_half_kernel(const float4* __restrict__ ue, const float4* __restrict__ ie,
                               uint2* __restrict__ dst) {
    int i = blockIdx.x * blockDim.x + threadIdx.x;
    int s = gridDim.x * blockDim.x;
    const int tot = NT * 16;
    for (; i < tot; i += s) {
        int row = i >> 4;
        float4 v = (row < NU) ? ue[i] : ie[i - NU * 16];
        uint2 u;
        u.x = h2u(v.x, v.y);
        u.y = h2u(v.z, v.w);
        dst[i] = u;
    }
}

// ---------------- CSR SpMM: 4 rows/warp, 8 lanes/row, unroll-4 pipeline ---------
__global__ void __launch_bounds__(256) csr_spmm4_kernel(
    const int* __restrict__ rowptr, const int2* __restrict__ cv,
    const __half* __restrict__ x, float* __restrict__ out, int nrows) {
    int warp = (blockIdx.x * blockDim.x + threadIdx.x) >> 5;
    int lane = threadIdx.x & 31;
    int g    = lane >> 3;
    int sub  = lane & 7;
    int row  = warp * 4 + g;
    bool valid = row < nrows;
    int start = valid ? __ldg(rowptr + row)     : 0;
    int end   = valid ? __ldg(rowptr + row + 1) : 0;

    float4 a0 = make_float4(0.f, 0.f, 0.f, 0.f);
    float4 a1 = make_float4(0.f, 0.f, 0.f, 0.f);

    int j = start;
    for (; j + 4 <= end; j += 4) {
        int2 q0 = __ldg(cv + j);
        int2 q1 = __ldg(cv + j + 1);
        int2 q2 = __ldg(cv + j + 2);
        int2 q3 = __ldg(cv + j + 3);
        uint4 x0 = __ldg(reinterpret_cast<const uint4*>(x + (size_t)q0.x * 64 + sub * 8));
        uint4 x1 = __ldg(reinterpret_cast<const uint4*>(x + (size_t)q1.x * 64 + sub * 8));
        uint4 x2 = __ldg(reinterpret_cast<const uint4*>(x + (size_t)q2.x * 64 + sub * 8));
        uint4 x3 = __ldg(reinterpret_cast<const uint4*>(x + (size_t)q3.x * 64 + sub * 8));
#define ACC(q, xv)                                                              \
        {                                                                       \
            float v = __int_as_float(q.y);                                      \
            float2 f0 = __half22float2(*reinterpret_cast<__half2*>(&xv.x));     \
            float2 f1 = __half22float2(*reinterpret_cast<__half2*>(&xv.y));     \
            float2 f2 = __half22float2(*reinterpret_cast<__half2*>(&xv.z));     \
            float2 f3 = __half22float2(*reinterpret_cast<__half2*>(&xv.w));     \
            a0.x = fmaf(v, f0.x, a0.x); a0.y = fmaf(v, f0.y, a0.y);             \
            a0.z = fmaf(v, f1.x, a0.z); a0.w = fmaf(v, f1.y, a0.w);             \
            a1.x = fmaf(v, f2.x, a1.x); a1.y = fmaf(v, f2.y, a1.y);             \
            a1.z = fmaf(v, f3.x, a1.z); a1.w = fmaf(v, f3.y, a1.w);             \
        }
        ACC(q0, x0) ACC(q1, x1) ACC(q2, x2) ACC(q3, x3)
    }
    for (; j < end; j++) {
        int2 q = __ldg(cv + j);
        uint4 xv = __ldg(reinterpret_cast<const uint4*>(x + (size_t)q.x * 64 + sub * 8));
        ACC(q, xv)
    }
#undef ACC
    if (valid) {
        float4* op = reinterpret_cast<float4*>(out + (size_t)row * 64 + sub * 8);
        op[0] = a0;
        op[1] = a1;
    }
}

// ---------------- GEMM: Y = act(X[R,64] @ W[64,64] + b), FFMA2 ------------------
template <int ACT, bool HOUT>
__global__ void __launch_bounds__(128) gemm64_kernel(
    const float* __restrict__ X, const float* __restrict__ W,
    const float* __restrict__ b, float* __restrict__ Y,
    __half* __restrict__ Yh, int R) {
    extern __shared__ float sm[];
    float* Ws = sm;           // 4096
    float* xs = sm + 4096;    // 8192 (transposed [k][tid])
    int tid = threadIdx.x;
    for (int i = tid; i < 4096; i += 128) Ws[i] = W[i];
    int row = blockIdx.x * 128 + tid;
    bool valid = row < R;
    if (valid) {
        const float4* xp = reinterpret_cast<const float4*>(X + (size_t)row * 64);
#pragma unroll
        for (int i = 0; i < 16; i++) {
            float4 t = xp[i];
            xs[(4 * i + 0) * 128 + tid] = t.x;
            xs[(4 * i + 1) * 128 + tid] = t.y;
            xs[(4 * i + 2) * 128 + tid] = t.z;
            xs[(4 * i + 3) * 128 + tid] = t.w;
        }
    }
    __syncthreads();
    if (!valid) return;

    ull acc2[32];
#pragma unroll
    for (int j = 0; j < 32; j++) acc2[j] = pk2(__ldg(b + 2 * j), __ldg(b + 2 * j + 1));

    for (int k = 0; k < 64; k++) {
        float xv = xs[k * 128 + tid];
        ull xv2 = pk2(xv, xv);
        const ulonglong2* wr = reinterpret_cast<const ulonglong2*>(Ws + k * 64);
#pragma unroll
        for (int j = 0; j < 16; j++) {
            ulonglong2 w = wr[j];
            fma2(acc2[2 * j + 0], xv2, w.x);
            fma2(acc2[2 * j + 1], xv2, w.y);
        }
    }

    float acc[64];
#pragma unroll
    for (int j = 0; j < 32; j++) upk2(acc2[j], acc[2 * j], acc[2 * j + 1]);
#pragma unroll
    for (int j = 0; j < 64; j++) {
        float a = acc[j];
        if (ACT == 1) a = a > 0.f ? a : expm1f(a);
        acc[j] = a;
    }

    if (HOUT) {
        uint4* yp = reinterpret_cast<uint4*>(Yh + (size_t)row * 64);
#pragma unroll
        for (int i = 0; i < 8; i++) {
            uint4 u;
            u.x = h2u(acc[8 * i + 0], acc[8 * i + 1]);
            u.y = h2u(acc[8 * i + 2], acc[8 * i + 3]);
            u.z = h2u(acc[8 * i + 4], acc[8 * i + 5]);
            u.w = h2u(acc[8 * i + 6], acc[8 * i + 7]);
            yp[i] = u;
        }
    } else {
        float4* yp = reinterpret_cast<float4*>(Y + (size_t)row * 64);
#pragma unroll
        for (int i = 0; i < 16; i++)
            yp[i] = make_float4(acc[4 * i + 0], acc[4 * i + 1], acc[4 * i + 2], acc[4 * i + 3]);
    }
}

// ---------------- Fused NGCF layer, FFMA2 ---------------------------------------
template <bool SPLIT>
__global__ void __launch_bounds__(128) layer_kernel(
    const float* __restrict__ Wg, const float* __restrict__ bg,
    const float* __restrict__ Wb, const float* __restrict__ bb,
    const float* __restrict__ eu, const float* __restrict__ ei, int kout) {
    extern __shared__ float sm[];
    float* Wgs = sm;            // 4096
    float* Wbs = sm + 4096;     // 4096
    float* ss  = sm + 8192;     // 8192 (transposed side [k][tid])
    int tid = threadIdx.x;
    for (int i = tid; i < 4096; i += 128) { Wgs[i] = Wg[i]; Wbs[i] = Wb[i]; }
    int row = blockIdx.x * 128 + tid;
    bool valid = row < NT;
    if (valid) {
        const float4* sp = reinterpret_cast<const float4*>(g_spmm + (size_t)row * 64);
#pragma unroll
        for (int i = 0; i < 16; i++) {
            float4 t = sp[i];
            ss[(4 * i + 0) * 128 + tid] = t.x;
            ss[(4 * i + 1) * 128 + tid] = t.y;
            ss[(4 * i + 2) * 128 + tid] = t.z;
            ss[(4 * i + 3) * 128 + tid] = t.w;
        }
    }
    __syncthreads();
    if (!valid) return;

    ull acc2[32];
#pragma unroll
    for (int j = 0; j < 32; j++)
        acc2[j] = pk2(__ldg(bg + 2 * j) + __ldg(bb + 2 * j),
                      __ldg(bg + 2 * j + 1) + __ldg(bb + 2 * j + 1));

    const float* erow;
    if (SPLIT) {
        erow = (row < NU) ? (eu + (size_t)row * 64) : (ei + (size_t)(row - NU) * 64);
    } else {
        erow = g_ego + (size_t)row * 64;
    }
    for (int k = 0; k < 64; k++) {
        float s = ss[k * 128 + tid];
        float p = s * __ldg(erow + k);
        ull s2 = pk2(s, s);
        ull p2 = pk2(p, p);
        const ulonglong2* wg = reinterpret_cast<const ulonglong2*>(Wgs + k * 64);
        const ulonglong2* wb = reinterpret_cast<const ulonglong2*>(Wbs + k * 64);
#pragma unroll
        for (int j = 0; j < 16; j++) {
            ulonglong2 a = wg[j];
            ulonglong2 c = wb[j];
            fma2(acc2[2 * j + 0], s2, a.x);
            fma2(acc2[2 * j + 1], s2, a.y);
            fma2(acc2[2 * j + 0], p2, c.x);
            fma2(acc2[2 * j + 1], p2, c.y);
        }
    }

    float acc[64];
#pragma unroll
    for (int j = 0; j < 32; j++) upk2(acc2[j], acc[2 * j], acc[2 * j + 1]);

    float ssum = 0.f;
#pragma unroll
    for (int j = 0; j < 64; j++) {
        float v = acc[j];
        v = v >= 0.f ? v : 0.2f * v;
        acc[j] = v;
        ssum += v * v;
    }
    float inv = 1.f / fmaxf(sqrtf(ssum), 1e-12f);

    float4* ep = reinterpret_cast<float4*>(g_ego + (size_t)row * 64);
    float4* ap = reinterpret_cast<float4*>(g_all + (size_t)row * 256 + (size_t)kout * 64);
#pragma unroll
    for (int i = 0; i < 16; i++) {
        float4 o = make_float4(acc[4 * i + 0], acc[4 * i + 1], acc[4 * i + 2], acc[4 * i + 3]);
        ep[i] = o;
        ap[i] = make_float4(o.x * inv, o.y * inv, o.z * inv, o.w * inv);
    }
    uint4* hp = reinterpret_cast<uint4*>(g_ego_h + (size_t)row * 64);
#pragma unroll
    for (int i = 0; i < 8; i++) {
        uint4 u;
        u.x = h2u(acc[8 * i + 0], acc[8 * i + 1]);
        u.y = h2u(acc[8 * i + 2], acc[8 * i + 3]);
        u.z = h2u(acc[8 * i + 4], acc[8 * i + 5]);
        u.w = h2u(acc[8 * i + 6], acc[8 * i + 7]);
        hp[i] = u;
    }
}

// ---------------- fill g_all block 0 (off critical path) ------------------------
__global__ void init_all0_kernel(const float4* __restrict__ ue, const float4* __restrict__ ie) {
    int i = blockIdx.x * blockDim.x + threadIdx.x;
    int s = gridDim.x * blockDim.x;
    const int tot = NT * 16;
    for (; i < tot; i += s) {
        int row = i >> 4;
        int c = i & 15;
        float4 v = (row < NU) ? ue[i] : ie[i - NU * 16];
        reinterpret_cast<float4*>(g_all)[(size_t)row * 64 + c] = v;
    }
}

// ---------------- final gather: out[12288, 320] ---------------------------------
__global__ void gather_kernel(const int* __restrict__ users, const int* __restrict__ pos,
                              const int* __restrict__ neg, float4* __restrict__ out) {
    int r = blockIdx.x;
    int tid = threadIdx.x;
    if (tid >= 80) return;
    const float4* allp;
    const float4* hp;
    if (r < 4096) {
        int u = __ldg(users + r);
        allp = reinterpret_cast<const float4*>(g_all + (size_t)u * 256);
        hp   = reinterpret_cast<const float4*>(g_uh + (size_t)u * 64);
    } else if (r < 8192) {
        int it = __ldg(pos + (r - 4096));
        allp = reinterpret_cast<const float4*>(g_all + ((size_t)NU + it) * 256);
        hp   = reinterpret_cast<const float4*>(g_ih + (size_t)it * 64);
    } else {
        int it = __ldg(neg + (r - 8192));
        allp = reinterpret_cast<const float4*>(g_all + ((size_t)NU + it) * 256);
        hp   = reinterpret_cast<const float4*>(g_ih + (size_t)it * 64);
    }
    float4 v;
    if (tid < 64) {
        v = allp[tid];
    } else {
        float4 h = hp[tid - 64];
        v = make_float4(fmaxf(h.x, 0.f), fmaxf(h.y, 0.f), fmaxf(h.z, 0.f), fmaxf(h.w, 0.f));
    }
    out[(size_t)r * 80 + tid] = v;
}

// ---------------- host ----------------------------------------------------------
static void build_csr(cudaStream_t st, const int* rows, const int* cols, const float* vals,
                      int nnz, int nrows, int* counts, int* off, int* rowptr,
                      ull* status, int* ticket, int2* cv) {
    int nb = (nrows + 1023) / 1024;
    reset_kernel<<<176, 256, 0, st>>>((int4*)counts, nrows / 4, status, ticket);
    hist_kernel<<<2048, 256, 0, st>>>(rows, counts, nnz);
    scan_lookback_kernel<<<nb, 1024, 0, st>>>(counts, rowptr, off, status, ticket, nrows, nnz);
    scatter_kernel<<<2048, 256, 0, st>>>(rows, cols, vals, off, cv, nnz);
}

#define GEMM_SMEM  (12288 * 4)   // 48 KB
#define LAYER_SMEM (16384 * 4)   // 64 KB

extern "C" void kernel_launch(void* const* d_in, const int* in_sizes, int n_in,
                              void* d_out, int out_size) {
    const int*   users    = (const int*)d_in[0];
    const int*   pos      = (const int*)d_in[1];
    const int*   neg      = (const int*)d_in[2];
    const int*   adj_r    = (const int*)d_in[3];
    const int*   adj_c    = (const int*)d_in[4];
    const float* adj_v    = (const float*)d_in[5];
    const int*   ug_r     = (const int*)d_in[6];
    const int*   ug_c     = (const int*)d_in[7];
    const float* ug_v     = (const float*)d_in[8];
    const int*   ig_r     = (const int*)d_in[9];
    const int*   ig_c     = (const int*)d_in[10];
    const float* ig_v     = (const float*)d_in[11];
    const float* user_emb = (const float*)d_in[12];
    const float* item_emb = (const float*)d_in[13];
    const float* W_gc     = (const float*)d_in[14];
    const float* b_gc     = (const float*)d_in[15];
    const float* W_bi     = (const float*)d_in[16];
    const float* b_bi     = (const float*)d_in[17];
    const float* Wu0      = (const float*)d_in[18];
    const float* bu0      = (const float*)d_in[19];
    const float* Wu1      = (const float*)d_in[20];
    const float* bu1      = (const float*)d_in[21];
    const float* Wi0      = (const float*)d_in[22];
    const float* bi0      = (const float*)d_in[23];
    const float* Wi1      = (const float*)d_in[24];
    const float* bi1      = (const float*)d_in[25];

    const int nnz_adj = in_sizes[3];
    const int nnz_ug  = in_sizes[6];
    const int nnz_ig  = in_sizes[9];

    static cudaStream_t s1 = nullptr, s2 = nullptr, s3 = nullptr;
    static cudaEvent_t evR = nullptr, ev1 = nullptr, ev2 = nullptr, ev3 = nullptr;
    if (s1 == nullptr) {
        cudaStreamCreateWithFlags(&s1, cudaStreamNonBlocking);
        cudaStreamCreateWithFlags(&s2, cudaStreamNonBlocking);
        cudaStreamCreateWithFlags(&s3, cudaStreamNonBlocking);
        cudaEventCreateWithFlags(&evR, cudaEventDisableTiming);
        cudaEventCreateWithFlags(&ev1, cudaEventDisableTiming);
        cudaEventCreateWithFlags(&ev2, cudaEventDisableTiming);
        cudaEventCreateWithFlags(&ev3, cudaEventDisableTiming);
        cudaFuncSetAttribute(gemm64_kernel<0, false>, cudaFuncAttributeMaxDynamicSharedMemorySize, GEMM_SMEM);
        cudaFuncSetAttribute(gemm64_kernel<1, true>,  cudaFuncAttributeMaxDynamicSharedMemorySize, GEMM_SMEM);
        cudaFuncSetAttribute(layer_kernel<true>,  cudaFuncAttributeMaxDynamicSharedMemorySize, LAYER_SMEM);
        cudaFuncSetAttribute(layer_kernel<false>, cudaFuncAttributeMaxDynamicSharedMemorySize, LAYER_SMEM);
    }

    float *spmm_p, *spmm_u, *spmm_i, *uh_p, *ih_p;
    __half *emb_h, *ego_h, *hid_uh, *hid_ih;
    cudaGetSymbolAddress((void**)&spmm_p, g_spmm);
    cudaGetSymbolAddress((void**)&spmm_u, g_spmm_u);
    cudaGetSymbolAddress((void**)&spmm_i, g_spmm_i);
    cudaGetSymbolAddress((void**)&uh_p,   g_uh);
    cudaGetSymbolAddress((void**)&ih_p,   g_ih);
    cudaGetSymbolAddress((void**)&emb_h,  g_emb_h);
    cudaGetSymbolAddress((void**)&ego_h,  g_ego_h);
    cudaGetSymbolAddress((void**)&hid_uh, g_hid_uh);
    cudaGetSymbolAddress((void**)&hid_ih, g_hid_ih);

    int *cnt_a, *cnt_u, *cnt_i, *off_a, *off_u, *off_i;
    int *adj_rp, *ug_rp, *ig_rp;
    int2 *adj_cv, *ug_cv, *ig_cv;
    ull *st_a, *st_u, *st_i;
    int *tk_a, *tk_u, *tk_i;
    cudaGetSymbolAddress((void**)&cnt_a, g_counts_a);
    cudaGetSymbolAddress((void**)&cnt_u, g_counts_u);
    cudaGetSymbolAddress((void**)&cnt_i, g_counts_i);
    cudaGetSymbolAddress((void**)&off_a, g_off_a);
    cudaGetSymbolAddress((void**)&off_u, g_off_u);
    cudaGetSymbolAddress((void**)&off_i, g_off_i);
    cudaGetSymbolAddress((void**)&adj_rp, g_adj_rp);
    cudaGetSymbolAddress((void**)&ug_rp,  g_ug_rp);
    cudaGetSymbolAddress((void**)&ig_rp,  g_ig_rp);
    cudaGetSymbolAddress((void**)&adj_cv, g_adj_cv);
    cudaGetSymbolAddress((void**)&ug_cv,  g_ug_cv);
    cudaGetSymbolAddress((void**)&ig_cv,  g_ig_cv);
    cudaGetSymbolAddress((void**)&st_a,   g_stat_a);
    cudaGetSymbolAddress((void**)&st_u,   g_stat_u);
    cudaGetSymbolAddress((void**)&st_i,   g_stat_i);
    cudaGetSymbolAddress((void**)&tk_a,   g_tkt_a);
    cudaGetSymbolAddress((void**)&tk_u,   g_tkt_u);
    cudaGetSymbolAddress((void**)&tk_i,   g_tkt_i);

    // ---- fork events first (side streams branch from capture origin) ----
    cudaEventRecord(evR, 0);
    cudaStreamWaitEvent(s1, evR, 0);
    cudaStreamWaitEvent(s2, evR, 0);
    cudaStreamWaitEvent(s3, evR, 0);

    // ---- s3: fp32 -> half embedding conversion (launch #1) ----
    to_half_kernel<<<1024, 256, 0, s3>>>((const float4*)user_emb, (const float4*)item_emb,
                                         (uint2*)emb_h);
    cudaEventRecord(ev3, s3);

    // ---- main stream: critical path FIRST (launches #2..#5 = adj build) ----
    build_csr(0, adj_r, adj_c, adj_v, nnz_adj, NT, cnt_a, off_a, adj_rp, st_a, tk_a, adj_cv);
    cudaStreamWaitEvent(0, ev3, 0);
    // launch #6: adj spmm (ncu -s 5 -c 1 window)
    csr_spmm4_kernel<<<(NT + 31) / 32, 256>>>(adj_rp, adj_cv, emb_h, spmm_p, NT);
    layer_kernel<true><<<(NT + 127) / 128, 128, LAYER_SMEM>>>(
        W_gc, b_gc, W_bi, b_bi, user_emb, item_emb, 1);
    for (int k = 1; k < 3; k++) {
        csr_spmm4_kernel<<<(NT + 31) / 32, 256>>>(adj_rp, adj_cv, ego_h, spmm_p, NT);
        layer_kernel<false><<<(NT + 127) / 128, 128, LAYER_SMEM>>>(
            W_gc + (size_t)k * 4096, b_gc + (size_t)k * 64,
            W_bi + (size_t)k * 4096, b_bi + (size_t)k * 64, nullptr, nullptr, k + 1);
    }

    // ---- branch 1 (s1): g_all block0 + user MLP path ----
    init_all0_kernel<<<1024, 256, 0, s1>>>((const float4*)user_emb, (const float4*)item_emb);
    build_csr(s1, ug_r, ug_c, ug_v, nnz_ug, NU, cnt_u, off_u, ug_rp, st_u, tk_u, ug_cv);
    cudaStreamWaitEvent(s1, ev3, 0);
    csr_spmm4_kernel<<<(NU + 31) / 32, 256, 0, s1>>>(ug_rp, ug_cv, emb_h, spmm_u, NU);
    gemm64_kernel<1, true><<<(NU + 127) / 128, 128, GEMM_SMEM, s1>>>(spmm_u, Wu0, bu0, nullptr, hid_uh, NU);
    csr_spmm4_kernel<<<(NU + 31) / 32, 256, 0, s1>>>(ug_rp, ug_cv, hid_uh, spmm_u, NU);
    gemm64_kernel<0, false><<<(NU + 127) / 128, 128, GEMM_SMEM, s1>>>(spmm_u, Wu1, bu1, uh_p, nullptr, NU);
    cudaEventRecord(ev1, s1);

    // ---- branch 2 (s2): item MLP path ----
    build_csr(s2, ig_r, ig_c, ig_v, nnz_ig, NI, cnt_i, off_i, ig_rp, st_i, tk_i, ig_cv);
    cudaStreamWaitEvent(s2, ev3, 0);
    csr_spmm4_kernel<<<(NI + 31) / 32, 256, 0, s2>>>(ig_rp, ig_cv, emb_h + (size_t)NU * 64, spmm_i, NI);
    gemm64_kernel<1, true><<<(NI + 127) / 128, 128, GEMM_SMEM, s2>>>(spmm_i, Wi0, bi0, nullptr, hid_ih, NI);
    csr_spmm4_kernel<<<(NI + 31) / 32, 256, 0, s2>>>(ig_rp, ig_cv, hid_ih, spmm_i, NI);
    gemm64_kernel<0, false><<<(NI + 127) / 128, 128, GEMM_SMEM, s2>>>(spmm_i, Wi1, bi1, ih_p, nullptr, NI);
    cudaEventRecord(ev2, s2);

    // ---- join + final gather ----
    cudaStreamWaitEvent(0, ev1, 0);
    cudaStreamWaitEvent(0, ev2, 0);
    gather_kernel<<<12288, 96>>>(users, pos, neg, (float4*)d_out);
}